// round 11
// baseline (speedup 1.0000x reference)
#include <cuda_runtime.h>
#include <cuda_fp16.h>
#include <cstdint>
#include <cstddef>

#define BATCH 4
#define SEQ   1024
#define EMB   1024
#define NH    16
#define HD    64
#define BH    (BATCH * NH)      // 64
#define MROWS (BATCH * SEQ)     // 4096

// ---- scratch (device globals: allocation-free per harness rules) ----
__device__ __half g_xh[(size_t)MROWS * EMB];          // rounded x (8 MB)
__device__ __half g_wqh[(size_t)EMB * EMB];           // 2 MB each
__device__ __half g_wkh[(size_t)EMB * EMB];
__device__ __half g_wvh[(size_t)EMB * EMB];
__device__ __half g_woh[(size_t)EMB * EMB];
__device__ __half g_qh[(size_t)BH * SEQ * HD];        // [B,H,S,D]
__device__ __half g_kh[(size_t)BH * SEQ * HD];        // [B,H,S,D]
__device__ __half g_vh[(size_t)BH * SEQ * HD];        // [B,H,D,S]  (TRANSPOSED)
__device__ __half g_oh[(size_t)MROWS * EMB];          // [B,S,H*D] concat

// fp16 mma m16n8k16, fp32 accumulate
__device__ __forceinline__ void mma16(float* c, const uint32_t* a, const uint32_t* b) {
    asm volatile(
        "mma.sync.aligned.m16n8k16.row.col.f32.f16.f16.f32 "
        "{%0,%1,%2,%3}, {%4,%5,%6,%7}, {%8,%9}, {%0,%1,%2,%3};\n"
        : "+f"(c[0]), "+f"(c[1]), "+f"(c[2]), "+f"(c[3])
        : "r"(a[0]), "r"(a[1]), "r"(a[2]), "r"(a[3]),
          "r"(b[0]), "r"(b[1]));
}

__device__ __forceinline__ void cp16(uint32_t dst, const void* src) {
    asm volatile("cp.async.cg.shared.global [%0], [%1], 16;\n"
                 :: "r"(dst), "l"(src));
}

__device__ __forceinline__ void ldsm4(uint32_t& r0, uint32_t& r1,
                                      uint32_t& r2, uint32_t& r3, uint32_t addr) {
    asm volatile("ldmatrix.sync.aligned.m8n8.x4.shared.b16 {%0,%1,%2,%3}, [%4];"
                 : "=r"(r0), "=r"(r1), "=r"(r2), "=r"(r3) : "r"(addr));
}

__device__ __forceinline__ uint32_t smem_u32(const void* p) {
    uint32_t a;
    asm("{ .reg .u64 t; cvta.to.shared.u64 t, %1; cvt.u32.u64 %0, t; }"
        : "=r"(a) : "l"(p));
    return a;
}

__device__ __forceinline__ uint32_t h2_bits(__half2 h) {
    return *reinterpret_cast<uint32_t*>(&h);
}

// ---- kernel 0: convert inputs to fp16 in scratch ----
__global__ void __launch_bounds__(256) convert_kernel(
    const float* __restrict__ x,
    const float* __restrict__ Wq, const float* __restrict__ Wk,
    const float* __restrict__ Wv, const float* __restrict__ Wo)
{
    const int z = blockIdx.z;
    const float* src;
    __half* dst;
    size_t n;
    if (z == 0)      { src = x;  dst = g_xh;  n = (size_t)MROWS * EMB; }
    else if (z == 1) { src = Wq; dst = g_wqh; n = (size_t)EMB * EMB; }
    else if (z == 2) { src = Wk; dst = g_wkh; n = (size_t)EMB * EMB; }
    else if (z == 3) { src = Wv; dst = g_wvh; n = (size_t)EMB * EMB; }
    else             { src = Wo; dst = g_woh; n = (size_t)EMB * EMB; }

    const size_t stride = (size_t)gridDim.x * blockDim.x * 4;
    for (size_t i = ((size_t)blockIdx.x * blockDim.x + threadIdx.x) * 4;
         i < n; i += stride) {
        float4 v = *reinterpret_cast<const float4*>(src + i);
        __half2* d2 = reinterpret_cast<__half2*>(dst + i);
        d2[0] = __floats2half2_rn(v.x, v.y);
        d2[1] = __floats2half2_rn(v.z, v.w);
    }
}

// ============================================================================
// 4-stage cp.async fp16 GEMM core, ldmatrix fragment loads.
// C[M,N] = A[M,K] * B[N,K]^T.  BM=BN=128, BK=32 halves, warp tile 64x32.
// Stage for chunk i+S-1 is issued BEFORE chunk-i compute (target buffer is
// chunk i-1's, protected by the top-of-iter barrier). Last S-1 chunks are
// peeled behind wait_group 0 (exact-count: empty groups complete instantly,
// so wait_group S-2 would NOT guarantee arrival in the tail).
// ============================================================================
#define GH_BM 128
#define GH_BN 128
#define GH_BK 32
#define GH_S  4
#define GH_LDT 20
#define GH_TILE (128 * GH_LDT)               // 2560 uints per operand per stage
#define GH_STG  (2 * GH_TILE)
#define GH_SMEM_BYTES (GH_S * GH_STG * 4)    // 81920 B
#define GH_MT 4
#define GH_NT 4

__device__ __forceinline__ void gemm_core_h(
    const __half* __restrict__ A,
    const __half* __restrict__ B,
    int Kdim, int m0, int n0,
    float (&acc)[GH_MT][GH_NT][4])
{
    extern __shared__ uint32_t smh[];
    const uint32_t sm_b = smem_u32(smh);

    const int tid  = threadIdx.x;
    const int lane = tid & 31;
    const int warp = tid >> 5;
    const int wm = (warp >> 2) * 64;         // 2 warp-rows
    const int wn = (warp & 3) * 32;          // 4 warp-cols
    // ldmatrix lane decomposition
    const int mat  = lane >> 3;
    const int rin  = lane & 7;
    const int a_lrow = (mat & 1) * 8 + rin;
    const int a_lcol = (mat >> 1) * 4;
    const int b_sel  = (mat >> 1);
    const int b_lcol = (mat & 1) * 4;

    auto stage = [&](int chunk) {
        const int s = chunk & (GH_S - 1);
        const uint32_t ab = sm_b + (uint32_t)(s * GH_STG) * 4;
        const uint32_t bb = ab + GH_TILE * 4;
        const int k0 = chunk * GH_BK;
        #pragma unroll
        for (int i = 0; i < 2; ++i) {
            int idx = tid + i * 256;
            int row = idx >> 2, q = idx & 3;
            cp16(ab + (uint32_t)(row * GH_LDT + q * 4) * 4,
                 A + (size_t)(m0 + row) * Kdim + k0 + q * 8);
            cp16(bb + (uint32_t)(row * GH_LDT + q * 4) * 4,
                 B + (size_t)(n0 + row) * Kdim + k0 + q * 8);
        }
    };

    auto compute = [&](int i) {
        const uint32_t ab = sm_b + (uint32_t)((i & (GH_S - 1)) * GH_STG) * 4;
        const uint32_t bb = ab + GH_TILE * 4;
        #pragma unroll
        for (int ks = 0; ks < 2; ++ks) {
            uint32_t af[GH_MT][4];
            uint32_t bf[GH_NT][2];
            #pragma unroll
            for (int mt = 0; mt < GH_MT; ++mt) {
                uint32_t ad = ab + (uint32_t)((wm + mt * 16 + a_lrow) * GH_LDT
                                              + ks * 8 + a_lcol) * 4;
                ldsm4(af[mt][0], af[mt][1], af[mt][2], af[mt][3], ad);
            }
            #pragma unroll
            for (int p = 0; p < 2; ++p) {
                uint32_t bd = bb + (uint32_t)((wn + (2 * p + b_sel) * 8 + rin) * GH_LDT
                                              + ks * 8 + b_lcol) * 4;
                ldsm4(bf[2 * p][0], bf[2 * p][1], bf[2 * p + 1][0], bf[2 * p + 1][1], bd);
            }
            #pragma unroll
            for (int mt = 0; mt < GH_MT; ++mt)
                #pragma unroll
                for (int nt = 0; nt < GH_NT; ++nt)
                    mma16(acc[mt][nt], af[mt], bf[nt]);
        }
    };

    const int nchunk = Kdim / GH_BK;
    #pragma unroll
    for (int c = 0; c < GH_S - 1; ++c) {
        stage(c);
        asm volatile("cp.async.commit_group;\n");
    }

    int i = 0;
    for (; i < nchunk - (GH_S - 1); ++i) {
        asm volatile("cp.async.wait_group %0;\n" :: "n"(GH_S - 2));
        __syncthreads();
        stage(i + GH_S - 1);
        asm volatile("cp.async.commit_group;\n");
        compute(i);
    }
    asm volatile("cp.async.wait_group 0;\n");
    __syncthreads();
    for (; i < nchunk; ++i) compute(i);
}

// ---- kernel 1: fused QKV projection (grid.z selects q/k/v) ----
// q,k stored [B,H,S,D]; v stored TRANSPOSED [B,H,D,S] for flash PV mma.
__global__ void __launch_bounds__(256, 2) qkv_kernel(
    const float* __restrict__ bq, const float* __restrict__ bk,
    const float* __restrict__ bv)
{
    const int z = blockIdx.z;
    const __half* W   = (z == 0) ? g_wqh : ((z == 1) ? g_wkh : g_wvh);
    const float* bptr = (z == 0) ? bq    : ((z == 1) ? bk    : bv);
    __half* out       = (z == 0) ? g_qh  : ((z == 1) ? g_kh  : g_vh);

    float acc[GH_MT][GH_NT][4] = {};
    const int m0 = blockIdx.x * GH_BM, n0 = blockIdx.y * GH_BN;
    gemm_core_h(g_xh, W, EMB, m0, n0, acc);

    const int lane = threadIdx.x & 31, warp = threadIdx.x >> 5;
    const int g = lane >> 2, tg = lane & 3;
    const int wm = (warp >> 2) * 64;
    const int wn = (warp & 3) * 32;

    #pragma unroll
    for (int mt = 0; mt < GH_MT; ++mt)
        #pragma unroll
        for (int nt = 0; nt < GH_NT; ++nt) {
            int r = m0 + wm + mt * 16 + g;
            int c = n0 + wn + nt * 8 + 2 * tg;       // even
            float v0 = acc[mt][nt][0] + bptr[c];
            float v1 = acc[mt][nt][1] + bptr[c + 1];
            float v2 = acc[mt][nt][2] + bptr[c];
            float v3 = acc[mt][nt][3] + bptr[c + 1];
            int h = c >> 6, d = c & 63;
            int b0 = r >> 10, s0 = r & 1023;
            int b1 = (r + 8) >> 10, s1 = (r + 8) & 1023;
            if (z < 2) {
                __half2* p0 = reinterpret_cast<__half2*>(
                    out + (((size_t)b0 * NH + h) * SEQ + s0) * HD + d);
                __half2* p1 = reinterpret_cast<__half2*>(
                    out + (((size_t)b1 * NH + h) * SEQ + s1) * HD + d);
                *p0 = __floats2half2_rn(v0, v1);
                *p1 = __floats2half2_rn(v2, v3);
            } else {
                out[(((size_t)b0 * NH + h) * HD + d) * SEQ + s0]     = __float2half_rn(v0);
                out[(((size_t)b0 * NH + h) * HD + d + 1) * SEQ + s0] = __float2half_rn(v1);
                out[(((size_t)b1 * NH + h) * HD + d) * SEQ + s1]     = __float2half_rn(v2);
                out[(((size_t)b1 * NH + h) * HD + d + 1) * SEQ + s1] = __float2half_rn(v3);
            }
        }
}

// ---- kernel 3: out = concat @ Wo^T + bo (fp32 output) ----
__global__ void __launch_bounds__(256, 2) oproj_kernel(
    const float* __restrict__ bo, float* __restrict__ out)
{
    float acc[GH_MT][GH_NT][4] = {};
    const int m0 = blockIdx.x * GH_BM, n0 = blockIdx.y * GH_BN;
    gemm_core_h(g_oh, g_woh, EMB, m0, n0, acc);

    const int lane = threadIdx.x & 31, warp = threadIdx.x >> 5;
    const int g = lane >> 2, tg = lane & 3;
    const int wm = (warp >> 2) * 64;
    const int wn = (warp & 3) * 32;
    #pragma unroll
    for (int mt = 0; mt < GH_MT; ++mt)
        #pragma unroll
        for (int nt = 0; nt < GH_NT; ++nt) {
            int r = m0 + wm + mt * 16 + g;
            int c = n0 + wn + nt * 8 + 2 * tg;
            out[(size_t)r * EMB + c]           = acc[mt][nt][0] + bo[c];
            out[(size_t)r * EMB + c + 1]       = acc[mt][nt][1] + bo[c + 1];
            out[(size_t)(r + 8) * EMB + c]     = acc[mt][nt][2] + bo[c];
            out[(size_t)(r + 8) * EMB + c + 1] = acc[mt][nt][3] + bo[c + 1];
        }
}

// ============================================================================
// kernel 2: fused flash attention, fp16 mma, ldmatrix fragment loads,
// DOUBLE-BUFFERED K/V tiles: tile t+1 staged at top of iter t; wait_group 1
// waits only on the previously staged tile (exact branch at tail).
// Qu[128][36], Ku[2][64][36], Vu[2][64][36] (d-major), Pu[128][36]
// ============================================================================
#define FA_BM 128
#define FA_BN 64
#define FA_NT (SEQ / FA_BN)     // 16 tiles
#define FA_LDT 36
#define FA_QS (128 * FA_LDT)
#define FA_KS (64 * FA_LDT)
#define FA_VS (64 * FA_LDT)
#define FA_PS (128 * FA_LDT)
#define FA_SMEM_BYTES ((FA_QS + 2 * FA_KS + 2 * FA_VS + FA_PS + 512) * 4)  // 75776 B

__global__ void __launch_bounds__(256, 2) flash_kernel()
{
    extern __shared__ uint32_t fsh[];
    uint32_t* Qu = fsh;
    uint32_t* Ku = Qu + FA_QS;              // [2][64][36]
    uint32_t* Vu = Ku + 2 * FA_KS;          // [2][64][36]
    uint32_t* Pu = Vu + 2 * FA_VS;
    float* redA  = (float*)(Pu + FA_PS);    // [2][128]
    float* redB  = redA + 256;              // [2][128]
    const uint32_t qu_b = smem_u32(Qu);
    const uint32_t ku_b = smem_u32(Ku);
    const uint32_t vu_b = smem_u32(Vu);
    const uint32_t pu_b = smem_u32(Pu);

    const int z  = blockIdx.z;
    const int m0 = blockIdx.x * FA_BM;
    const __half* Qh = g_qh + (size_t)z * SEQ * HD;
    const __half* Kh = g_kh + (size_t)z * SEQ * HD;
    const __half* Vh = g_vh + (size_t)z * HD * SEQ;   // [D][S]

    const int tid  = threadIdx.x;
    const int lane = tid & 31, warp = tid >> 5;
    const int g = lane >> 2, tg = lane & 3;
    const int mw = warp >> 1, nw = warp & 1;
    const int wm = mw * 32;
    const int wn = nw * 32;
    const int mat  = lane >> 3, rin = lane & 7;
    const int a_lrow = (mat & 1) * 8 + rin;
    const int a_lcol = (mat >> 1) * 4;
    const int b_sel  = (mat >> 1);
    const int b_lcol = (mat & 1) * 4;

    auto stage_kv = [&](int t) {
        const uint32_t kb = ku_b + (uint32_t)((t & 1) * FA_KS) * 4;
        const uint32_t vb = vu_b + (uint32_t)((t & 1) * FA_VS) * 4;
        const int n0 = t * FA_BN;
        #pragma unroll
        for (int i = 0; i < 2; ++i) {
            int idx = tid + i * 256;
            int rr = idx >> 3, q = idx & 7;
            cp16(kb + (uint32_t)(rr * FA_LDT + q * 4) * 4,
                 Kh + (size_t)(n0 + rr) * HD + q * 8);
            cp16(vb + (uint32_t)(rr * FA_LDT + q * 4) * 4,
                 Vh + (size_t)rr * SEQ + n0 + q * 8);
        }
    };

    // stage Q + tile 0 in group G0
    #pragma unroll
    for (int i = 0; i < 4; ++i) {
        int idx = tid + i * 256;
        int r = idx >> 3, q = idx & 7;
        cp16(qu_b + (uint32_t)(r * FA_LDT + q * 4) * 4,
             Qh + (size_t)(m0 + r) * HD + q * 8);
    }
    stage_kv(0);
    asm volatile("cp.async.commit_group;\n");

    float acc_o[2][4][4] = {};
    float m_st[2][2] = {{-1e30f, -1e30f}, {-1e30f, -1e30f}};
    float l_st[2][2] = {};

    for (int t = 0; t < FA_NT; ++t) {
        __syncthreads();   // all warps done reading buf (t+1)&1 (iter t-1) and Pu

        if (t + 1 < FA_NT) {
            stage_kv(t + 1);
            asm volatile("cp.async.commit_group;\n");
            asm volatile("cp.async.wait_group 1;\n");   // tile t arrived
        } else {
            asm volatile("cp.async.wait_group 0;\n");
        }
        __syncthreads();   // tile t visible to all warps

        const uint32_t kub = ku_b + (uint32_t)((t & 1) * FA_KS) * 4;
        const uint32_t vub = vu_b + (uint32_t)((t & 1) * FA_VS) * 4;

        // ---- S = Q K^T (4 k16 steps over D=64) ----
        float acc_s[2][4][4] = {};
        #pragma unroll
        for (int ks = 0; ks < 4; ++ks) {
            uint32_t af[2][4];
            uint32_t bf[4][2];
            #pragma unroll
            for (int mt = 0; mt < 2; ++mt) {
                uint32_t ad = qu_b + (uint32_t)((wm + mt * 16 + a_lrow) * FA_LDT
                                                + ks * 8 + a_lcol) * 4;
                ldsm4(af[mt][0], af[mt][1], af[mt][2], af[mt][3], ad);
            }
            #pragma unroll
            for (int p = 0; p < 2; ++p) {
                uint32_t bd = kub + (uint32_t)((wn + (2 * p + b_sel) * 8 + rin) * FA_LDT
                                               + ks * 8 + b_lcol) * 4;
                ldsm4(bf[2 * p][0], bf[2 * p][1], bf[2 * p + 1][0], bf[2 * p + 1][1], bd);
            }
            #pragma unroll
            for (int mt = 0; mt < 2; ++mt)
                #pragma unroll
                for (int nt = 0; nt < 4; ++nt)
                    mma16(acc_s[mt][nt], af[mt], bf[nt]);
        }
        #pragma unroll
        for (int mt = 0; mt < 2; ++mt)
            #pragma unroll
            for (int nt = 0; nt < 4; ++nt)
                #pragma unroll
                for (int e = 0; e < 4; ++e)
                    acc_s[mt][nt][e] *= 0.125f;

        // ---- row max (quad shuffle + cross-nw smem) ----
        #pragma unroll
        for (int mt = 0; mt < 2; ++mt)
            #pragma unroll
            for (int h = 0; h < 2; ++h) {
                float m = -1e30f;
                #pragma unroll
                for (int nt = 0; nt < 4; ++nt)
                    m = fmaxf(m, fmaxf(acc_s[mt][nt][2 * h], acc_s[mt][nt][2 * h + 1]));
                m = fmaxf(m, __shfl_xor_sync(0xffffffffu, m, 1));
                m = fmaxf(m, __shfl_xor_sync(0xffffffffu, m, 2));
                if (tg == 0) redA[nw * 128 + wm + mt * 16 + g + 8 * h] = m;
            }
        __syncthreads();

        // ---- online softmax + write P (half2 packed) ----
        #pragma unroll
        for (int mt = 0; mt < 2; ++mt)
            #pragma unroll
            for (int h = 0; h < 2; ++h) {
                int row = wm + mt * 16 + g + 8 * h;
                float m = fmaxf(redA[row], redA[128 + row]);
                float mnew = fmaxf(m_st[mt][h], m);
                float scale = __expf(m_st[mt][h] - mnew);
                m_st[mt][h] = mnew;
                l_st[mt][h] *= scale;
                #pragma unroll
                for (int nt = 0; nt < 4; ++nt) {
                    acc_o[mt][nt][2 * h]     *= scale;
                    acc_o[mt][nt][2 * h + 1] *= scale;
                }
                float rs = 0.f;
                #pragma unroll
                for (int nt = 0; nt < 4; ++nt) {
                    float p0 = __expf(acc_s[mt][nt][2 * h]     - mnew);
                    float p1 = __expf(acc_s[mt][nt][2 * h + 1] - mnew);
                    rs += p0 + p1;
                    Pu[row * FA_LDT + (wn >> 1) + nt * 4 + tg] =
                        h2_bits(__floats2half2_rn(p0, p1));
                }
                rs += __shfl_xor_sync(0xffffffffu, rs, 1);
                rs += __shfl_xor_sync(0xffffffffu, rs, 2);
                if (tg == 0) redB[nw * 128 + row] = rs;
            }
        __syncthreads();   // P + redB visible across warps

        #pragma unroll
        for (int mt = 0; mt < 2; ++mt)
            #pragma unroll
            for (int h = 0; h < 2; ++h) {
                int row = wm + mt * 16 + g + 8 * h;
                l_st[mt][h] += redB[row] + redB[128 + row];
            }

        // ---- O += P V (4 k16 steps over 64 keys) ----
        #pragma unroll
        for (int ks = 0; ks < 4; ++ks) {
            uint32_t af[2][4];
            uint32_t bf[4][2];
            #pragma unroll
            for (int mt = 0; mt < 2; ++mt) {
                uint32_t ad = pu_b + (uint32_t)((wm + mt * 16 + a_lrow) * FA_LDT
                                                + ks * 8 + a_lcol) * 4;
                ldsm4(af[mt][0], af[mt][1], af[mt][2], af[mt][3], ad);
            }
            #pragma unroll
            for (int p = 0; p < 2; ++p) {
                uint32_t bd = vub + (uint32_t)((wn + (2 * p + b_sel) * 8 + rin) * FA_LDT
                                               + ks * 8 + b_lcol) * 4;
                ldsm4(bf[2 * p][0], bf[2 * p][1], bf[2 * p + 1][0], bf[2 * p + 1][1], bd);
            }
            #pragma unroll
            for (int mt = 0; mt < 2; ++mt)
                #pragma unroll
                for (int nt = 0; nt < 4; ++nt)
                    mma16(acc_o[mt][nt], af[mt], bf[nt]);
        }
    }

    // ---- epilogue: O /= l, half2 stores into concat layout [B,S,H*D] ----
    const int b = z >> 4, h = z & 15;
    #pragma unroll
    for (int mt = 0; mt < 2; ++mt) {
        float inv0 = 1.0f / l_st[mt][0];
        float inv1 = 1.0f / l_st[mt][1];
        #pragma unroll
        for (int nt = 0; nt < 4; ++nt) {
            int s0 = m0 + wm + mt * 16 + g;
            int d0 = wn + nt * 8 + 2 * tg;           // even
            size_t base0 = ((size_t)(b * SEQ + s0)) * EMB + h * HD + d0;
            size_t base1 = ((size_t)(b * SEQ + s0 + 8)) * EMB + h * HD + d0;
            *reinterpret_cast<__half2*>(g_oh + base0) =
                __floats2half2_rn(acc_o[mt][nt][0] * inv0, acc_o[mt][nt][1] * inv0);
            *reinterpret_cast<__half2*>(g_oh + base1) =
                __floats2half2_rn(acc_o[mt][nt][2] * inv1, acc_o[mt][nt][3] * inv1);
        }
    }
}

extern "C" void kernel_launch(void* const* d_in, const int* in_sizes, int n_in,
                              void* d_out, int out_size)
{
    const float* x  = (const float*)d_in[0];
    const float* Wq = (const float*)d_in[1];
    const float* bq = (const float*)d_in[2];
    const float* Wk = (const float*)d_in[3];
    const float* bk = (const float*)d_in[4];
    const float* Wv = (const float*)d_in[5];
    const float* bv = (const float*)d_in[6];
    const float* Wo = (const float*)d_in[7];
    const float* bo = (const float*)d_in[8];
    float* out = (float*)d_out;

    cudaFuncSetAttribute(qkv_kernel,
                         cudaFuncAttributeMaxDynamicSharedMemorySize, GH_SMEM_BYTES);
    cudaFuncSetAttribute(oproj_kernel,
                         cudaFuncAttributeMaxDynamicSharedMemorySize, GH_SMEM_BYTES);
    cudaFuncSetAttribute(flash_kernel,
                         cudaFuncAttributeMaxDynamicSharedMemorySize, FA_SMEM_BYTES);

    convert_kernel<<<dim3(1024, 1, 5), 256>>>(x, Wq, Wk, Wv, Wo);
    qkv_kernel<<<dim3(MROWS / GH_BM, EMB / GH_BN, 3), 256, GH_SMEM_BYTES>>>(bq, bk, bv);
    flash_kernel<<<dim3(SEQ / FA_BM, 1, BH), 256, FA_SMEM_BYTES>>>();
    oproj_kernel<<<dim3(MROWS / GH_BM, EMB / GH_BN, 1), 256, GH_SMEM_BYTES>>>(bo, out);
}

// round 12
// speedup vs baseline: 1.0957x; 1.0957x over previous
#include <cuda_runtime.h>
#include <cuda_fp16.h>
#include <cstdint>
#include <cstddef>

#define BATCH 4
#define SEQ   1024
#define EMB   1024
#define NH    16
#define HD    64
#define BH    (BATCH * NH)      // 64
#define MROWS (BATCH * SEQ)     // 4096

// ---- scratch (device globals: allocation-free per harness rules) ----
__device__ __half g_xh[(size_t)MROWS * EMB];          // rounded x (8 MB)
__device__ __half g_wqh[(size_t)EMB * EMB];           // 2 MB each
__device__ __half g_wkh[(size_t)EMB * EMB];
__device__ __half g_wvh[(size_t)EMB * EMB];
__device__ __half g_woh[(size_t)EMB * EMB];
__device__ __half g_qh[(size_t)BH * SEQ * HD];        // [B,H,S,D]
__device__ __half g_kh[(size_t)BH * SEQ * HD];        // [B,H,S,D]
__device__ __half g_vh[(size_t)BH * SEQ * HD];        // [B,H,D,S]  (TRANSPOSED)
__device__ __half g_oh[(size_t)MROWS * EMB];          // [B,S,H*D] concat

// fp16 mma m16n8k16, fp32 accumulate
__device__ __forceinline__ void mma16(float* c, const uint32_t* a, const uint32_t* b) {
    asm volatile(
        "mma.sync.aligned.m16n8k16.row.col.f32.f16.f16.f32 "
        "{%0,%1,%2,%3}, {%4,%5,%6,%7}, {%8,%9}, {%0,%1,%2,%3};\n"
        : "+f"(c[0]), "+f"(c[1]), "+f"(c[2]), "+f"(c[3])
        : "r"(a[0]), "r"(a[1]), "r"(a[2]), "r"(a[3]),
          "r"(b[0]), "r"(b[1]));
}

__device__ __forceinline__ void cp16(uint32_t dst, const void* src) {
    asm volatile("cp.async.cg.shared.global [%0], [%1], 16;\n"
                 :: "r"(dst), "l"(src));
}

__device__ __forceinline__ void ldsm4(uint32_t& r0, uint32_t& r1,
                                      uint32_t& r2, uint32_t& r3, uint32_t addr) {
    asm volatile("ldmatrix.sync.aligned.m8n8.x4.shared.b16 {%0,%1,%2,%3}, [%4];"
                 : "=r"(r0), "=r"(r1), "=r"(r2), "=r"(r3) : "r"(addr));
}

__device__ __forceinline__ uint32_t smem_u32(const void* p) {
    uint32_t a;
    asm("{ .reg .u64 t; cvta.to.shared.u64 t, %1; cvt.u32.u64 %0, t; }"
        : "=r"(a) : "l"(p));
    return a;
}

__device__ __forceinline__ uint32_t h2_bits(__half2 h) {
    return *reinterpret_cast<uint32_t*>(&h);
}

// ---- kernel 0: convert inputs to fp16 in scratch ----
__global__ void __launch_bounds__(256) convert_kernel(
    const float* __restrict__ x,
    const float* __restrict__ Wq, const float* __restrict__ Wk,
    const float* __restrict__ Wv, const float* __restrict__ Wo)
{
    const int z = blockIdx.z;
    const float* src;
    __half* dst;
    size_t n;
    if (z == 0)      { src = x;  dst = g_xh;  n = (size_t)MROWS * EMB; }
    else if (z == 1) { src = Wq; dst = g_wqh; n = (size_t)EMB * EMB; }
    else if (z == 2) { src = Wk; dst = g_wkh; n = (size_t)EMB * EMB; }
    else if (z == 3) { src = Wv; dst = g_wvh; n = (size_t)EMB * EMB; }
    else             { src = Wo; dst = g_woh; n = (size_t)EMB * EMB; }

    const size_t stride = (size_t)gridDim.x * blockDim.x * 4;
    for (size_t i = ((size_t)blockIdx.x * blockDim.x + threadIdx.x) * 4;
         i < n; i += stride) {
        float4 v = *reinterpret_cast<const float4*>(src + i);
        __half2* d2 = reinterpret_cast<__half2*>(dst + i);
        d2[0] = __floats2half2_rn(v.x, v.y);
        d2[1] = __floats2half2_rn(v.z, v.w);
    }
}

// ============================================================================
// 4-stage cp.async fp16 GEMM core, ldmatrix fragment loads.
// C[M,N] = A[M,K] * B[N,K]^T.  BM=BN=128, BK=32 halves, warp tile 64x32.
// Compute-first in-loop ordering (R10, measured faster); last S-1 chunks
// peeled behind wait_group 0 (empty groups complete instantly, so wait S-2
// would not guarantee arrival in the tail).
// ============================================================================
#define GH_BM 128
#define GH_BN 128
#define GH_BK 32
#define GH_S  4
#define GH_LDT 20
#define GH_TILE (128 * GH_LDT)               // 2560 uints per operand per stage
#define GH_STG  (2 * GH_TILE)
#define GH_SMEM_BYTES (GH_S * GH_STG * 4)    // 81920 B
#define GH_MT 4
#define GH_NT 4

__device__ __forceinline__ void gemm_core_h(
    const __half* __restrict__ A,
    const __half* __restrict__ B,
    int Kdim, int m0, int n0,
    float (&acc)[GH_MT][GH_NT][4])
{
    extern __shared__ uint32_t smh[];
    const uint32_t sm_b = smem_u32(smh);

    const int tid  = threadIdx.x;
    const int lane = tid & 31;
    const int warp = tid >> 5;
    const int wm = (warp >> 2) * 64;
    const int wn = (warp & 3) * 32;
    const int mat  = lane >> 3;
    const int rin  = lane & 7;
    const int a_lrow = (mat & 1) * 8 + rin;
    const int a_lcol = (mat >> 1) * 4;
    const int b_sel  = (mat >> 1);
    const int b_lcol = (mat & 1) * 4;

    auto stage = [&](int chunk) {
        const int s = chunk & (GH_S - 1);
        const uint32_t ab = sm_b + (uint32_t)(s * GH_STG) * 4;
        const uint32_t bb = ab + GH_TILE * 4;
        const int k0 = chunk * GH_BK;
        #pragma unroll
        for (int i = 0; i < 2; ++i) {
            int idx = tid + i * 256;
            int row = idx >> 2, q = idx & 3;
            cp16(ab + (uint32_t)(row * GH_LDT + q * 4) * 4,
                 A + (size_t)(m0 + row) * Kdim + k0 + q * 8);
            cp16(bb + (uint32_t)(row * GH_LDT + q * 4) * 4,
                 B + (size_t)(n0 + row) * Kdim + k0 + q * 8);
        }
    };

    auto compute = [&](int i) {
        const uint32_t ab = sm_b + (uint32_t)((i & (GH_S - 1)) * GH_STG) * 4;
        const uint32_t bb = ab + GH_TILE * 4;
        #pragma unroll
        for (int ks = 0; ks < 2; ++ks) {
            uint32_t af[GH_MT][4];
            uint32_t bf[GH_NT][2];
            #pragma unroll
            for (int mt = 0; mt < GH_MT; ++mt) {
                uint32_t ad = ab + (uint32_t)((wm + mt * 16 + a_lrow) * GH_LDT
                                              + ks * 8 + a_lcol) * 4;
                ldsm4(af[mt][0], af[mt][1], af[mt][2], af[mt][3], ad);
            }
            #pragma unroll
            for (int p = 0; p < 2; ++p) {
                uint32_t bd = bb + (uint32_t)((wn + (2 * p + b_sel) * 8 + rin) * GH_LDT
                                              + ks * 8 + b_lcol) * 4;
                ldsm4(bf[2 * p][0], bf[2 * p][1], bf[2 * p + 1][0], bf[2 * p + 1][1], bd);
            }
            #pragma unroll
            for (int mt = 0; mt < GH_MT; ++mt)
                #pragma unroll
                for (int nt = 0; nt < GH_NT; ++nt)
                    mma16(acc[mt][nt], af[mt], bf[nt]);
        }
    };

    const int nchunk = Kdim / GH_BK;
    #pragma unroll
    for (int c = 0; c < GH_S - 1; ++c) {
        stage(c);
        asm volatile("cp.async.commit_group;\n");
    }

    int i = 0;
    for (; i < nchunk - (GH_S - 1); ++i) {
        asm volatile("cp.async.wait_group %0;\n" :: "n"(GH_S - 2));
        __syncthreads();
        compute(i);
        stage(i + GH_S - 1);
        asm volatile("cp.async.commit_group;\n");
    }
    asm volatile("cp.async.wait_group 0;\n");
    __syncthreads();
    for (; i < nchunk; ++i) compute(i);
}

// ---- kernel 1: fused QKV projection (grid.z selects q/k/v) ----
// q,k stored [B,H,S,D]; v stored TRANSPOSED [B,H,D,S] for flash PV mma.
__global__ void __launch_bounds__(256, 2) qkv_kernel(
    const float* __restrict__ bq, const float* __restrict__ bk,
    const float* __restrict__ bv)
{
    const int z = blockIdx.z;
    const __half* W   = (z == 0) ? g_wqh : ((z == 1) ? g_wkh : g_wvh);
    const float* bptr = (z == 0) ? bq    : ((z == 1) ? bk    : bv);
    __half* out       = (z == 0) ? g_qh  : ((z == 1) ? g_kh  : g_vh);

    float acc[GH_MT][GH_NT][4] = {};
    const int m0 = blockIdx.x * GH_BM, n0 = blockIdx.y * GH_BN;
    gemm_core_h(g_xh, W, EMB, m0, n0, acc);

    const int lane = threadIdx.x & 31, warp = threadIdx.x >> 5;
    const int g = lane >> 2, tg = lane & 3;
    const int wm = (warp >> 2) * 64;
    const int wn = (warp & 3) * 32;

    #pragma unroll
    for (int mt = 0; mt < GH_MT; ++mt)
        #pragma unroll
        for (int nt = 0; nt < GH_NT; ++nt) {
            int r = m0 + wm + mt * 16 + g;
            int c = n0 + wn + nt * 8 + 2 * tg;       // even
            float v0 = acc[mt][nt][0] + bptr[c];
            float v1 = acc[mt][nt][1] + bptr[c + 1];
            float v2 = acc[mt][nt][2] + bptr[c];
            float v3 = acc[mt][nt][3] + bptr[c + 1];
            int h = c >> 6, d = c & 63;
            int b0 = r >> 10, s0 = r & 1023;
            int b1 = (r + 8) >> 10, s1 = (r + 8) & 1023;
            if (z < 2) {
                __half2* p0 = reinterpret_cast<__half2*>(
                    out + (((size_t)b0 * NH + h) * SEQ + s0) * HD + d);
                __half2* p1 = reinterpret_cast<__half2*>(
                    out + (((size_t)b1 * NH + h) * SEQ + s1) * HD + d);
                *p0 = __floats2half2_rn(v0, v1);
                *p1 = __floats2half2_rn(v2, v3);
            } else {
                out[(((size_t)b0 * NH + h) * HD + d) * SEQ + s0]     = __float2half_rn(v0);
                out[(((size_t)b0 * NH + h) * HD + d + 1) * SEQ + s0] = __float2half_rn(v1);
                out[(((size_t)b1 * NH + h) * HD + d) * SEQ + s1]     = __float2half_rn(v2);
                out[(((size_t)b1 * NH + h) * HD + d + 1) * SEQ + s1] = __float2half_rn(v3);
            }
        }
}

// ---- kernel 3: out = concat @ Wo^T + bo (fp32 output) ----
__global__ void __launch_bounds__(256, 2) oproj_kernel(
    const float* __restrict__ bo, float* __restrict__ out)
{
    float acc[GH_MT][GH_NT][4] = {};
    const int m0 = blockIdx.x * GH_BM, n0 = blockIdx.y * GH_BN;
    gemm_core_h(g_oh, g_woh, EMB, m0, n0, acc);

    const int lane = threadIdx.x & 31, warp = threadIdx.x >> 5;
    const int g = lane >> 2, tg = lane & 3;
    const int wm = (warp >> 2) * 64;
    const int wn = (warp & 3) * 32;
    #pragma unroll
    for (int mt = 0; mt < GH_MT; ++mt)
        #pragma unroll
        for (int nt = 0; nt < GH_NT; ++nt) {
            int r = m0 + wm + mt * 16 + g;
            int c = n0 + wn + nt * 8 + 2 * tg;
            out[(size_t)r * EMB + c]           = acc[mt][nt][0] + bo[c];
            out[(size_t)r * EMB + c + 1]       = acc[mt][nt][1] + bo[c + 1];
            out[(size_t)(r + 8) * EMB + c]     = acc[mt][nt][2] + bo[c];
            out[(size_t)(r + 8) * EMB + c + 1] = acc[mt][nt][3] + bo[c + 1];
        }
}

// ============================================================================
// kernel 2: fused flash attention — FA2-style warp-row ownership.
// Each of 8 warps owns 16 full rows (S tile 16x64, O tile 16x64).
// Softmax entirely warp-local (quad shuffles); P stays IN REGISTERS:
// the S accumulator fragment layout IS the PV A-fragment layout.
// Qu[128][36], Ku[2][64][36], Vu[2][64][36] (d-major). No P smem, no red smem.
// ============================================================================
#define FA_BM 128
#define FA_BN 64
#define FA_NT_TILES (SEQ / FA_BN)   // 16
#define FA_LDT 36
#define FA_QS (128 * FA_LDT)
#define FA_KS (64 * FA_LDT)
#define FA_VS (64 * FA_LDT)
#define FA_SMEM_BYTES ((FA_QS + 2 * FA_KS + 2 * FA_VS) * 4)   // 55296 B

__global__ void __launch_bounds__(256, 2) flash_kernel()
{
    extern __shared__ uint32_t fsh[];
    uint32_t* Qu = fsh;
    uint32_t* Ku = Qu + FA_QS;              // [2][64][36]
    uint32_t* Vu = Ku + 2 * FA_KS;          // [2][64][36]
    const uint32_t qu_b = smem_u32(Qu);
    const uint32_t ku_b = smem_u32(Ku);
    const uint32_t vu_b = smem_u32(Vu);

    const int z  = blockIdx.z;
    const int m0 = blockIdx.x * FA_BM;
    const __half* Qh = g_qh + (size_t)z * SEQ * HD;
    const __half* Kh = g_kh + (size_t)z * SEQ * HD;
    const __half* Vh = g_vh + (size_t)z * HD * SEQ;   // [D][S]

    const int tid  = threadIdx.x;
    const int lane = tid & 31, warp = tid >> 5;
    const int g = lane >> 2, tg = lane & 3;
    const int mat  = lane >> 3, rin = lane & 7;
    const int a_lrow = (mat & 1) * 8 + rin;
    const int a_lcol = (mat >> 1) * 4;
    const int b_sel  = (mat >> 1);
    const int b_lcol = (mat & 1) * 4;
    const int wrow = warp * 16;             // this warp's 16 rows

    auto stage_kv = [&](int t) {
        const uint32_t kb = ku_b + (uint32_t)((t & 1) * FA_KS) * 4;
        const uint32_t vb = vu_b + (uint32_t)((t & 1) * FA_VS) * 4;
        const int n0 = t * FA_BN;
        #pragma unroll
        for (int i = 0; i < 2; ++i) {
            int idx = tid + i * 256;
            int rr = idx >> 3, q = idx & 7;
            cp16(kb + (uint32_t)(rr * FA_LDT + q * 4) * 4,
                 Kh + (size_t)(n0 + rr) * HD + q * 8);
            cp16(vb + (uint32_t)(rr * FA_LDT + q * 4) * 4,
                 Vh + (size_t)rr * SEQ + n0 + q * 8);
        }
    };

    // stage Q + tile 0
    #pragma unroll
    for (int i = 0; i < 4; ++i) {
        int idx = tid + i * 256;
        int r = idx >> 3, q = idx & 7;
        cp16(qu_b + (uint32_t)(r * FA_LDT + q * 4) * 4,
             Qh + (size_t)(m0 + r) * HD + q * 8);
    }
    stage_kv(0);
    asm volatile("cp.async.commit_group;\n");

    float acc_o[8][4] = {};
    float m_st[2] = {-1e30f, -1e30f};
    float l_st[2] = {0.f, 0.f};

    for (int t = 0; t < FA_NT_TILES; ++t) {
        __syncthreads();   // all warps done reading buf (t+1)&1 from iter t-1

        if (t + 1 < FA_NT_TILES) {
            stage_kv(t + 1);
            asm volatile("cp.async.commit_group;\n");
            asm volatile("cp.async.wait_group 1;\n");   // tile t arrived
        } else {
            asm volatile("cp.async.wait_group 0;\n");
        }
        __syncthreads();   // tile t visible to all warps

        const uint32_t kub = ku_b + (uint32_t)((t & 1) * FA_KS) * 4;
        const uint32_t vub = vu_b + (uint32_t)((t & 1) * FA_VS) * 4;

        // ---- S = Q_w (16x64) K^T : 4 k16 steps over D=64, NT=8 key tiles ----
        float acc_s[8][4] = {};
        #pragma unroll
        for (int ks = 0; ks < 4; ++ks) {
            uint32_t af[4];
            uint32_t bf[8][2];
            uint32_t ad = qu_b + (uint32_t)((wrow + a_lrow) * FA_LDT
                                            + ks * 8 + a_lcol) * 4;
            ldsm4(af[0], af[1], af[2], af[3], ad);
            #pragma unroll
            for (int p = 0; p < 4; ++p) {
                uint32_t bd = kub + (uint32_t)(((2 * p + b_sel) * 8 + rin) * FA_LDT
                                               + ks * 8 + b_lcol) * 4;
                ldsm4(bf[2 * p][0], bf[2 * p][1], bf[2 * p + 1][0], bf[2 * p + 1][1], bd);
            }
            #pragma unroll
            for (int nt = 0; nt < 8; ++nt)
                mma16(acc_s[nt], af, bf[nt]);
        }
        #pragma unroll
        for (int nt = 0; nt < 8; ++nt)
            #pragma unroll
            for (int e = 0; e < 4; ++e)
                acc_s[nt][e] *= 0.125f;

        // ---- warp-local online softmax; P packed into registers ----
        uint32_t plo[8], phi[8];
        #pragma unroll
        for (int h = 0; h < 2; ++h) {
            float m = -1e30f;
            #pragma unroll
            for (int nt = 0; nt < 8; ++nt)
                m = fmaxf(m, fmaxf(acc_s[nt][2 * h], acc_s[nt][2 * h + 1]));
            m = fmaxf(m, __shfl_xor_sync(0xffffffffu, m, 1));
            m = fmaxf(m, __shfl_xor_sync(0xffffffffu, m, 2));
            float mnew = fmaxf(m_st[h], m);
            float sc = __expf(m_st[h] - mnew);
            m_st[h] = mnew;
            l_st[h] *= sc;
            #pragma unroll
            for (int nt = 0; nt < 8; ++nt) {
                acc_o[nt][2 * h]     *= sc;
                acc_o[nt][2 * h + 1] *= sc;
            }
            float rs = 0.f;
            #pragma unroll
            for (int nt = 0; nt < 8; ++nt) {
                float p0 = __expf(acc_s[nt][2 * h]     - mnew);
                float p1 = __expf(acc_s[nt][2 * h + 1] - mnew);
                rs += p0 + p1;
                uint32_t pk = h2_bits(__floats2half2_rn(p0, p1));
                if (h == 0) plo[nt] = pk; else phi[nt] = pk;
            }
            rs += __shfl_xor_sync(0xffffffffu, rs, 1);
            rs += __shfl_xor_sync(0xffffffffu, rs, 2);
            l_st[h] += rs;
        }

        // ---- O += P V : P A-fragments straight from registers ----
        #pragma unroll
        for (int ks = 0; ks < 4; ++ks) {
            uint32_t af[4] = { plo[2 * ks], phi[2 * ks],
                               plo[2 * ks + 1], phi[2 * ks + 1] };
            uint32_t bf[8][2];
            #pragma unroll
            for (int p = 0; p < 4; ++p) {
                uint32_t bd = vub + (uint32_t)(((2 * p + b_sel) * 8 + rin) * FA_LDT
                                               + ks * 8 + b_lcol) * 4;
                ldsm4(bf[2 * p][0], bf[2 * p][1], bf[2 * p + 1][0], bf[2 * p + 1][1], bd);
            }
            #pragma unroll
            for (int nt = 0; nt < 8; ++nt)
                mma16(acc_o[nt], af, bf[nt]);
        }
    }

    // ---- epilogue: O /= l, half2 stores into concat layout [B,S,H*D] ----
    const int b = z >> 4, h = z & 15;
    const float inv0 = 1.0f / l_st[0];
    const float inv1 = 1.0f / l_st[1];
    const int s0 = m0 + wrow + g;
    #pragma unroll
    for (int nt = 0; nt < 8; ++nt) {
        int d0 = nt * 8 + 2 * tg;               // even
        size_t base0 = ((size_t)(b * SEQ + s0)) * EMB + h * HD + d0;
        size_t base1 = ((size_t)(b * SEQ + s0 + 8)) * EMB + h * HD + d0;
        *reinterpret_cast<__half2*>(g_oh + base0) =
            __floats2half2_rn(acc_o[nt][0] * inv0, acc_o[nt][1] * inv0);
        *reinterpret_cast<__half2*>(g_oh + base1) =
            __floats2half2_rn(acc_o[nt][2] * inv1, acc_o[nt][3] * inv1);
    }
}

extern "C" void kernel_launch(void* const* d_in, const int* in_sizes, int n_in,
                              void* d_out, int out_size)
{
    const float* x  = (const float*)d_in[0];
    const float* Wq = (const float*)d_in[1];
    const float* bq = (const float*)d_in[2];
    const float* Wk = (const float*)d_in[3];
    const float* bk = (const float*)d_in[4];
    const float* Wv = (const float*)d_in[5];
    const float* bv = (const float*)d_in[6];
    const float* Wo = (const float*)d_in[7];
    const float* bo = (const float*)d_in[8];
    float* out = (float*)d_out;

    cudaFuncSetAttribute(qkv_kernel,
                         cudaFuncAttributeMaxDynamicSharedMemorySize, GH_SMEM_BYTES);
    cudaFuncSetAttribute(oproj_kernel,
                         cudaFuncAttributeMaxDynamicSharedMemorySize, GH_SMEM_BYTES);
    cudaFuncSetAttribute(flash_kernel,
                         cudaFuncAttributeMaxDynamicSharedMemorySize, FA_SMEM_BYTES);

    convert_kernel<<<dim3(1024, 1, 5), 256>>>(x, Wq, Wk, Wv, Wo);
    qkv_kernel<<<dim3(MROWS / GH_BM, EMB / GH_BN, 3), 256, GH_SMEM_BYTES>>>(bq, bk, bv);
    flash_kernel<<<dim3(SEQ / FA_BM, 1, BH), 256, FA_SMEM_BYTES>>>();
    oproj_kernel<<<dim3(MROWS / GH_BM, EMB / GH_BN, 1), 256, GH_SMEM_BYTES>>>(bo, out);
}

// round 13
// speedup vs baseline: 1.1079x; 1.0111x over previous
#include <cuda_runtime.h>
#include <cuda_fp16.h>
#include <cstdint>
#include <cstddef>

#define BATCH 4
#define SEQ   1024
#define EMB   1024
#define NH    16
#define HD    64
#define BH    (BATCH * NH)      // 64
#define MROWS (BATCH * SEQ)     // 4096

// ---- scratch (device globals: allocation-free per harness rules) ----
__device__ __half g_xh[(size_t)MROWS * EMB];          // rounded x (8 MB)
__device__ __half g_wqh[(size_t)EMB * EMB];           // 2 MB each
__device__ __half g_wkh[(size_t)EMB * EMB];
__device__ __half g_wvh[(size_t)EMB * EMB];
__device__ __half g_woh[(size_t)EMB * EMB];
__device__ __half g_qh[(size_t)BH * SEQ * HD];        // [B,H,S,D]
__device__ __half g_kh[(size_t)BH * SEQ * HD];        // [B,H,S,D]
__device__ __half g_vh[(size_t)BH * SEQ * HD];        // [B,H,D,S]  (TRANSPOSED)
__device__ __half g_oh[(size_t)MROWS * EMB];          // [B,S,H*D] concat

// fp16 mma m16n8k16, fp32 accumulate
__device__ __forceinline__ void mma16(float* c, const uint32_t* a, const uint32_t* b) {
    asm volatile(
        "mma.sync.aligned.m16n8k16.row.col.f32.f16.f16.f32 "
        "{%0,%1,%2,%3}, {%4,%5,%6,%7}, {%8,%9}, {%0,%1,%2,%3};\n"
        : "+f"(c[0]), "+f"(c[1]), "+f"(c[2]), "+f"(c[3])
        : "r"(a[0]), "r"(a[1]), "r"(a[2]), "r"(a[3]),
          "r"(b[0]), "r"(b[1]));
}

__device__ __forceinline__ void cp16(uint32_t dst, const void* src) {
    asm volatile("cp.async.cg.shared.global [%0], [%1], 16;\n"
                 :: "r"(dst), "l"(src));
}

__device__ __forceinline__ void ldsm4(uint32_t& r0, uint32_t& r1,
                                      uint32_t& r2, uint32_t& r3, uint32_t addr) {
    asm volatile("ldmatrix.sync.aligned.m8n8.x4.shared.b16 {%0,%1,%2,%3}, [%4];"
                 : "=r"(r0), "=r"(r1), "=r"(r2), "=r"(r3) : "r"(addr));
}

__device__ __forceinline__ uint32_t smem_u32(const void* p) {
    uint32_t a;
    asm("{ .reg .u64 t; cvta.to.shared.u64 t, %1; cvt.u32.u64 %0, t; }"
        : "=r"(a) : "l"(p));
    return a;
}

__device__ __forceinline__ uint32_t h2_bits(__half2 h) {
    return *reinterpret_cast<uint32_t*>(&h);
}

// ---- kernel 0: convert inputs to fp16 in scratch ----
__global__ void __launch_bounds__(256) convert_kernel(
    const float* __restrict__ x,
    const float* __restrict__ Wq, const float* __restrict__ Wk,
    const float* __restrict__ Wv, const float* __restrict__ Wo)
{
    const int z = blockIdx.z;
    const float* src;
    __half* dst;
    size_t n;
    if (z == 0)      { src = x;  dst = g_xh;  n = (size_t)MROWS * EMB; }
    else if (z == 1) { src = Wq; dst = g_wqh; n = (size_t)EMB * EMB; }
    else if (z == 2) { src = Wk; dst = g_wkh; n = (size_t)EMB * EMB; }
    else if (z == 3) { src = Wv; dst = g_wvh; n = (size_t)EMB * EMB; }
    else             { src = Wo; dst = g_woh; n = (size_t)EMB * EMB; }

    const size_t stride = (size_t)gridDim.x * blockDim.x * 4;
    for (size_t i = ((size_t)blockIdx.x * blockDim.x + threadIdx.x) * 4;
         i < n; i += stride) {
        float4 v = *reinterpret_cast<const float4*>(src + i);
        __half2* d2 = reinterpret_cast<__half2*>(dst + i);
        d2[0] = __floats2half2_rn(v.x, v.y);
        d2[1] = __floats2half2_rn(v.z, v.w);
    }
}

// ============================================================================
// 4-stage cp.async fp16 GEMM core, ldmatrix loads, WARP TILE 64x64.
// C[M,N] = A[M,K] * B[N,K]^T.  BM=BN=128, BK=32, 128 threads (2x2 warps).
// smem bytes/mma: 160 (was 192); A cross-warp redundancy 2x (was 4x).
// Compute-first ordering; tail peeled behind wait_group 0.
// ============================================================================
#define GH_BM 128
#define GH_BN 128
#define GH_BK 32
#define GH_S  4
#define GH_THR 128
#define GH_LDT 20
#define GH_TILE (128 * GH_LDT)               // 2560 uints per operand per stage
#define GH_STG  (2 * GH_TILE)
#define GH_SMEM_BYTES (GH_S * GH_STG * 4)    // 81920 B
#define GH_MT 4
#define GH_NT 8

__device__ __forceinline__ void gemm_core_h(
    const __half* __restrict__ A,
    const __half* __restrict__ B,
    int Kdim, int m0, int n0,
    float (&acc)[GH_MT][GH_NT][4])
{
    extern __shared__ uint32_t smh[];
    const uint32_t sm_b = smem_u32(smh);

    const int tid  = threadIdx.x;
    const int lane = tid & 31;
    const int warp = tid >> 5;               // 0..3
    const int wm = (warp >> 1) * 64;         // 2 warp-rows
    const int wn = (warp & 1) * 64;          // 2 warp-cols
    const int mat  = lane >> 3;
    const int rin  = lane & 7;
    const int a_lrow = (mat & 1) * 8 + rin;
    const int a_lcol = (mat >> 1) * 4;
    const int b_sel  = (mat >> 1);
    const int b_lcol = (mat & 1) * 4;

    auto stage = [&](int chunk) {
        const int s = chunk & (GH_S - 1);
        const uint32_t ab = sm_b + (uint32_t)(s * GH_STG) * 4;
        const uint32_t bb = ab + GH_TILE * 4;
        const int k0 = chunk * GH_BK;
        #pragma unroll
        for (int i = 0; i < 4; ++i) {        // 128 rows x 4 cp16 per operand
            int idx = tid + i * GH_THR;
            int row = idx >> 2, q = idx & 3;
            cp16(ab + (uint32_t)(row * GH_LDT + q * 4) * 4,
                 A + (size_t)(m0 + row) * Kdim + k0 + q * 8);
            cp16(bb + (uint32_t)(row * GH_LDT + q * 4) * 4,
                 B + (size_t)(n0 + row) * Kdim + k0 + q * 8);
        }
    };

    auto compute = [&](int i) {
        const uint32_t ab = sm_b + (uint32_t)((i & (GH_S - 1)) * GH_STG) * 4;
        const uint32_t bb = ab + GH_TILE * 4;
        #pragma unroll
        for (int ks = 0; ks < 2; ++ks) {
            uint32_t af[GH_MT][4];
            uint32_t bf[GH_NT][2];
            #pragma unroll
            for (int mt = 0; mt < GH_MT; ++mt) {
                uint32_t ad = ab + (uint32_t)((wm + mt * 16 + a_lrow) * GH_LDT
                                              + ks * 8 + a_lcol) * 4;
                ldsm4(af[mt][0], af[mt][1], af[mt][2], af[mt][3], ad);
            }
            #pragma unroll
            for (int p = 0; p < 4; ++p) {
                uint32_t bd = bb + (uint32_t)((wn + (2 * p + b_sel) * 8 + rin) * GH_LDT
                                              + ks * 8 + b_lcol) * 4;
                ldsm4(bf[2 * p][0], bf[2 * p][1], bf[2 * p + 1][0], bf[2 * p + 1][1], bd);
            }
            #pragma unroll
            for (int mt = 0; mt < GH_MT; ++mt)
                #pragma unroll
                for (int nt = 0; nt < GH_NT; ++nt)
                    mma16(acc[mt][nt], af[mt], bf[nt]);
        }
    };

    const int nchunk = Kdim / GH_BK;
    #pragma unroll
    for (int c = 0; c < GH_S - 1; ++c) {
        stage(c);
        asm volatile("cp.async.commit_group;\n");
    }

    int i = 0;
    for (; i < nchunk - (GH_S - 1); ++i) {
        asm volatile("cp.async.wait_group %0;\n" :: "n"(GH_S - 2));
        __syncthreads();
        compute(i);
        stage(i + GH_S - 1);
        asm volatile("cp.async.commit_group;\n");
    }
    asm volatile("cp.async.wait_group 0;\n");
    __syncthreads();
    for (; i < nchunk; ++i) compute(i);
}

// ---- kernel 1: fused QKV projection (grid.z selects q/k/v) ----
// q,k stored [B,H,S,D]; v stored TRANSPOSED [B,H,D,S] for flash PV mma.
__global__ void __launch_bounds__(GH_THR, 2) qkv_kernel(
    const float* __restrict__ bq, const float* __restrict__ bk,
    const float* __restrict__ bv)
{
    const int z = blockIdx.z;
    const __half* W   = (z == 0) ? g_wqh : ((z == 1) ? g_wkh : g_wvh);
    const float* bptr = (z == 0) ? bq    : ((z == 1) ? bk    : bv);
    __half* out       = (z == 0) ? g_qh  : ((z == 1) ? g_kh  : g_vh);

    float acc[GH_MT][GH_NT][4] = {};
    const int m0 = blockIdx.x * GH_BM, n0 = blockIdx.y * GH_BN;
    gemm_core_h(g_xh, W, EMB, m0, n0, acc);

    const int lane = threadIdx.x & 31, warp = threadIdx.x >> 5;
    const int g = lane >> 2, tg = lane & 3;
    const int wm = (warp >> 1) * 64;
    const int wn = (warp & 1) * 64;

    #pragma unroll
    for (int mt = 0; mt < GH_MT; ++mt)
        #pragma unroll
        for (int nt = 0; nt < GH_NT; ++nt) {
            int r = m0 + wm + mt * 16 + g;
            int c = n0 + wn + nt * 8 + 2 * tg;       // even
            float v0 = acc[mt][nt][0] + bptr[c];
            float v1 = acc[mt][nt][1] + bptr[c + 1];
            float v2 = acc[mt][nt][2] + bptr[c];
            float v3 = acc[mt][nt][3] + bptr[c + 1];
            int h = c >> 6, d = c & 63;
            int b0 = r >> 10, s0 = r & 1023;
            int b1 = (r + 8) >> 10, s1 = (r + 8) & 1023;
            if (z < 2) {
                __half2* p0 = reinterpret_cast<__half2*>(
                    out + (((size_t)b0 * NH + h) * SEQ + s0) * HD + d);
                __half2* p1 = reinterpret_cast<__half2*>(
                    out + (((size_t)b1 * NH + h) * SEQ + s1) * HD + d);
                *p0 = __floats2half2_rn(v0, v1);
                *p1 = __floats2half2_rn(v2, v3);
            } else {
                out[(((size_t)b0 * NH + h) * HD + d) * SEQ + s0]     = __float2half_rn(v0);
                out[(((size_t)b0 * NH + h) * HD + d + 1) * SEQ + s0] = __float2half_rn(v1);
                out[(((size_t)b1 * NH + h) * HD + d) * SEQ + s1]     = __float2half_rn(v2);
                out[(((size_t)b1 * NH + h) * HD + d + 1) * SEQ + s1] = __float2half_rn(v3);
            }
        }
}

// ---- kernel 3: out = concat @ Wo^T + bo (fp32 output) ----
__global__ void __launch_bounds__(GH_THR, 2) oproj_kernel(
    const float* __restrict__ bo, float* __restrict__ out)
{
    float acc[GH_MT][GH_NT][4] = {};
    const int m0 = blockIdx.x * GH_BM, n0 = blockIdx.y * GH_BN;
    gemm_core_h(g_oh, g_woh, EMB, m0, n0, acc);

    const int lane = threadIdx.x & 31, warp = threadIdx.x >> 5;
    const int g = lane >> 2, tg = lane & 3;
    const int wm = (warp >> 1) * 64;
    const int wn = (warp & 1) * 64;
    #pragma unroll
    for (int mt = 0; mt < GH_MT; ++mt)
        #pragma unroll
        for (int nt = 0; nt < GH_NT; ++nt) {
            int r = m0 + wm + mt * 16 + g;
            int c = n0 + wn + nt * 8 + 2 * tg;
            out[(size_t)r * EMB + c]           = acc[mt][nt][0] + bo[c];
            out[(size_t)r * EMB + c + 1]       = acc[mt][nt][1] + bo[c + 1];
            out[(size_t)(r + 8) * EMB + c]     = acc[mt][nt][2] + bo[c];
            out[(size_t)(r + 8) * EMB + c + 1] = acc[mt][nt][3] + bo[c + 1];
        }
}

// ============================================================================
// kernel 2: fused flash attention — FA2-style warp-row ownership (unchanged R12)
// ============================================================================
#define FA_BM 128
#define FA_BN 64
#define FA_NT_TILES (SEQ / FA_BN)   // 16
#define FA_LDT 36
#define FA_QS (128 * FA_LDT)
#define FA_KS (64 * FA_LDT)
#define FA_VS (64 * FA_LDT)
#define FA_SMEM_BYTES ((FA_QS + 2 * FA_KS + 2 * FA_VS) * 4)   // 55296 B

__global__ void __launch_bounds__(256, 2) flash_kernel()
{
    extern __shared__ uint32_t fsh[];
    uint32_t* Qu = fsh;
    uint32_t* Ku = Qu + FA_QS;              // [2][64][36]
    uint32_t* Vu = Ku + 2 * FA_KS;          // [2][64][36]
    const uint32_t qu_b = smem_u32(Qu);
    const uint32_t ku_b = smem_u32(Ku);
    const uint32_t vu_b = smem_u32(Vu);

    const int z  = blockIdx.z;
    const int m0 = blockIdx.x * FA_BM;
    const __half* Qh = g_qh + (size_t)z * SEQ * HD;
    const __half* Kh = g_kh + (size_t)z * SEQ * HD;
    const __half* Vh = g_vh + (size_t)z * HD * SEQ;   // [D][S]

    const int tid  = threadIdx.x;
    const int lane = tid & 31, warp = tid >> 5;
    const int g = lane >> 2, tg = lane & 3;
    const int mat  = lane >> 3, rin = lane & 7;
    const int a_lrow = (mat & 1) * 8 + rin;
    const int a_lcol = (mat >> 1) * 4;
    const int b_sel  = (mat >> 1);
    const int b_lcol = (mat & 1) * 4;
    const int wrow = warp * 16;             // this warp's 16 rows

    auto stage_kv = [&](int t) {
        const uint32_t kb = ku_b + (uint32_t)((t & 1) * FA_KS) * 4;
        const uint32_t vb = vu_b + (uint32_t)((t & 1) * FA_VS) * 4;
        const int n0 = t * FA_BN;
        #pragma unroll
        for (int i = 0; i < 2; ++i) {
            int idx = tid + i * 256;
            int rr = idx >> 3, q = idx & 7;
            cp16(kb + (uint32_t)(rr * FA_LDT + q * 4) * 4,
                 Kh + (size_t)(n0 + rr) * HD + q * 8);
            cp16(vb + (uint32_t)(rr * FA_LDT + q * 4) * 4,
                 Vh + (size_t)rr * SEQ + n0 + q * 8);
        }
    };

    // stage Q + tile 0
    #pragma unroll
    for (int i = 0; i < 4; ++i) {
        int idx = tid + i * 256;
        int r = idx >> 3, q = idx & 7;
        cp16(qu_b + (uint32_t)(r * FA_LDT + q * 4) * 4,
             Qh + (size_t)(m0 + r) * HD + q * 8);
    }
    stage_kv(0);
    asm volatile("cp.async.commit_group;\n");

    float acc_o[8][4] = {};
    float m_st[2] = {-1e30f, -1e30f};
    float l_st[2] = {0.f, 0.f};

    for (int t = 0; t < FA_NT_TILES; ++t) {
        __syncthreads();   // all warps done reading buf (t+1)&1 from iter t-1

        if (t + 1 < FA_NT_TILES) {
            stage_kv(t + 1);
            asm volatile("cp.async.commit_group;\n");
            asm volatile("cp.async.wait_group 1;\n");   // tile t arrived
        } else {
            asm volatile("cp.async.wait_group 0;\n");
        }
        __syncthreads();   // tile t visible to all warps

        const uint32_t kub = ku_b + (uint32_t)((t & 1) * FA_KS) * 4;
        const uint32_t vub = vu_b + (uint32_t)((t & 1) * FA_VS) * 4;

        // ---- S = Q_w (16x64) K^T ----
        float acc_s[8][4] = {};
        #pragma unroll
        for (int ks = 0; ks < 4; ++ks) {
            uint32_t af[4];
            uint32_t bf[8][2];
            uint32_t ad = qu_b + (uint32_t)((wrow + a_lrow) * FA_LDT
                                            + ks * 8 + a_lcol) * 4;
            ldsm4(af[0], af[1], af[2], af[3], ad);
            #pragma unroll
            for (int p = 0; p < 4; ++p) {
                uint32_t bd = kub + (uint32_t)(((2 * p + b_sel) * 8 + rin) * FA_LDT
                                               + ks * 8 + b_lcol) * 4;
                ldsm4(bf[2 * p][0], bf[2 * p][1], bf[2 * p + 1][0], bf[2 * p + 1][1], bd);
            }
            #pragma unroll
            for (int nt = 0; nt < 8; ++nt)
                mma16(acc_s[nt], af, bf[nt]);
        }
        #pragma unroll
        for (int nt = 0; nt < 8; ++nt)
            #pragma unroll
            for (int e = 0; e < 4; ++e)
                acc_s[nt][e] *= 0.125f;

        // ---- warp-local online softmax; P packed into registers ----
        uint32_t plo[8], phi[8];
        #pragma unroll
        for (int h = 0; h < 2; ++h) {
            float m = -1e30f;
            #pragma unroll
            for (int nt = 0; nt < 8; ++nt)
                m = fmaxf(m, fmaxf(acc_s[nt][2 * h], acc_s[nt][2 * h + 1]));
            m = fmaxf(m, __shfl_xor_sync(0xffffffffu, m, 1));
            m = fmaxf(m, __shfl_xor_sync(0xffffffffu, m, 2));
            float mnew = fmaxf(m_st[h], m);
            float sc = __expf(m_st[h] - mnew);
            m_st[h] = mnew;
            l_st[h] *= sc;
            #pragma unroll
            for (int nt = 0; nt < 8; ++nt) {
                acc_o[nt][2 * h]     *= sc;
                acc_o[nt][2 * h + 1] *= sc;
            }
            float rs = 0.f;
            #pragma unroll
            for (int nt = 0; nt < 8; ++nt) {
                float p0 = __expf(acc_s[nt][2 * h]     - mnew);
                float p1 = __expf(acc_s[nt][2 * h + 1] - mnew);
                rs += p0 + p1;
                uint32_t pk = h2_bits(__floats2half2_rn(p0, p1));
                if (h == 0) plo[nt] = pk; else phi[nt] = pk;
            }
            rs += __shfl_xor_sync(0xffffffffu, rs, 1);
            rs += __shfl_xor_sync(0xffffffffu, rs, 2);
            l_st[h] += rs;
        }

        // ---- O += P V : P A-fragments straight from registers ----
        #pragma unroll
        for (int ks = 0; ks < 4; ++ks) {
            uint32_t af[4] = { plo[2 * ks], phi[2 * ks],
                               plo[2 * ks + 1], phi[2 * ks + 1] };
            uint32_t bf[8][2];
            #pragma unroll
            for (int p = 0; p < 4; ++p) {
                uint32_t bd = vub + (uint32_t)(((2 * p + b_sel) * 8 + rin) * FA_LDT
                                               + ks * 8 + b_lcol) * 4;
                ldsm4(bf[2 * p][0], bf[2 * p][1], bf[2 * p + 1][0], bf[2 * p + 1][1], bd);
            }
            #pragma unroll
            for (int nt = 0; nt < 8; ++nt)
                mma16(acc_o[nt], af, bf[nt]);
        }
    }

    // ---- epilogue: O /= l, half2 stores into concat layout [B,S,H*D] ----
    const int b = z >> 4, h = z & 15;
    const float inv0 = 1.0f / l_st[0];
    const float inv1 = 1.0f / l_st[1];
    const int s0 = m0 + wrow + g;
    #pragma unroll
    for (int nt = 0; nt < 8; ++nt) {
        int d0 = nt * 8 + 2 * tg;               // even
        size_t base0 = ((size_t)(b * SEQ + s0)) * EMB + h * HD + d0;
        size_t base1 = ((size_t)(b * SEQ + s0 + 8)) * EMB + h * HD + d0;
        *reinterpret_cast<__half2*>(g_oh + base0) =
            __floats2half2_rn(acc_o[nt][0] * inv0, acc_o[nt][1] * inv0);
        *reinterpret_cast<__half2*>(g_oh + base1) =
            __floats2half2_rn(acc_o[nt][2] * inv1, acc_o[nt][3] * inv1);
    }
}

extern "C" void kernel_launch(void* const* d_in, const int* in_sizes, int n_in,
                              void* d_out, int out_size)
{
    const float* x  = (const float*)d_in[0];
    const float* Wq = (const float*)d_in[1];
    const float* bq = (const float*)d_in[2];
    const float* Wk = (const float*)d_in[3];
    const float* bk = (const float*)d_in[4];
    const float* Wv = (const float*)d_in[5];
    const float* bv = (const float*)d_in[6];
    const float* Wo = (const float*)d_in[7];
    const float* bo = (const float*)d_in[8];
    float* out = (float*)d_out;

    cudaFuncSetAttribute(qkv_kernel,
                         cudaFuncAttributeMaxDynamicSharedMemorySize, GH_SMEM_BYTES);
    cudaFuncSetAttribute(oproj_kernel,
                         cudaFuncAttributeMaxDynamicSharedMemorySize, GH_SMEM_BYTES);
    cudaFuncSetAttribute(flash_kernel,
                         cudaFuncAttributeMaxDynamicSharedMemorySize, FA_SMEM_BYTES);

    convert_kernel<<<dim3(1024, 1, 5), 256>>>(x, Wq, Wk, Wv, Wo);
    qkv_kernel<<<dim3(MROWS / GH_BM, EMB / GH_BN, 3), GH_THR, GH_SMEM_BYTES>>>(bq, bk, bv);
    flash_kernel<<<dim3(SEQ / FA_BM, 1, BH), 256, FA_SMEM_BYTES>>>();
    oproj_kernel<<<dim3(MROWS / GH_BM, EMB / GH_BN, 1), GH_THR, GH_SMEM_BYTES>>>(bo, out);
}

// round 14
// speedup vs baseline: 1.1187x; 1.0098x over previous
#include <cuda_runtime.h>
#include <cuda_fp16.h>
#include <cstdint>
#include <cstddef>

#define BATCH 4
#define SEQ   1024
#define EMB   1024
#define NH    16
#define HD    64
#define BH    (BATCH * NH)      // 64
#define MROWS (BATCH * SEQ)     // 4096

// ---- scratch (device globals: allocation-free per harness rules) ----
__device__ __half g_xh[(size_t)MROWS * EMB];          // rounded x (8 MB)
__device__ __half g_wqh[(size_t)EMB * EMB];           // 2 MB each
__device__ __half g_wkh[(size_t)EMB * EMB];
__device__ __half g_wvh[(size_t)EMB * EMB];
__device__ __half g_woh[(size_t)EMB * EMB];
__device__ __half g_qh[(size_t)BH * SEQ * HD];        // [B,H,S,D]
__device__ __half g_kh[(size_t)BH * SEQ * HD];        // [B,H,S,D]
__device__ __half g_vh[(size_t)BH * SEQ * HD];        // [B,H,D,S]  (TRANSPOSED)
__device__ __half g_oh[(size_t)MROWS * EMB];          // [B,S,H*D] concat

// fp16 mma m16n8k16, fp32 accumulate
__device__ __forceinline__ void mma16(float* c, const uint32_t* a, const uint32_t* b) {
    asm volatile(
        "mma.sync.aligned.m16n8k16.row.col.f32.f16.f16.f32 "
        "{%0,%1,%2,%3}, {%4,%5,%6,%7}, {%8,%9}, {%0,%1,%2,%3};\n"
        : "+f"(c[0]), "+f"(c[1]), "+f"(c[2]), "+f"(c[3])
        : "r"(a[0]), "r"(a[1]), "r"(a[2]), "r"(a[3]),
          "r"(b[0]), "r"(b[1]));
}

__device__ __forceinline__ void cp16(uint32_t dst, const void* src) {
    asm volatile("cp.async.cg.shared.global [%0], [%1], 16;\n"
                 :: "r"(dst), "l"(src));
}

__device__ __forceinline__ void ldsm4(uint32_t& r0, uint32_t& r1,
                                      uint32_t& r2, uint32_t& r3, uint32_t addr) {
    asm volatile("ldmatrix.sync.aligned.m8n8.x4.shared.b16 {%0,%1,%2,%3}, [%4];"
                 : "=r"(r0), "=r"(r1), "=r"(r2), "=r"(r3) : "r"(addr));
}

__device__ __forceinline__ uint32_t smem_u32(const void* p) {
    uint32_t a;
    asm("{ .reg .u64 t; cvta.to.shared.u64 t, %1; cvt.u32.u64 %0, t; }"
        : "=r"(a) : "l"(p));
    return a;
}

__device__ __forceinline__ uint32_t h2_bits(__half2 h) {
    return *reinterpret_cast<uint32_t*>(&h);
}

// ---- kernel 0: convert inputs to fp16 in scratch ----
__global__ void __launch_bounds__(256) convert_kernel(
    const float* __restrict__ x,
    const float* __restrict__ Wq, const float* __restrict__ Wk,
    const float* __restrict__ Wv, const float* __restrict__ Wo)
{
    const int z = blockIdx.z;
    const float* src;
    __half* dst;
    size_t n;
    if (z == 0)      { src = x;  dst = g_xh;  n = (size_t)MROWS * EMB; }
    else if (z == 1) { src = Wq; dst = g_wqh; n = (size_t)EMB * EMB; }
    else if (z == 2) { src = Wk; dst = g_wkh; n = (size_t)EMB * EMB; }
    else if (z == 3) { src = Wv; dst = g_wvh; n = (size_t)EMB * EMB; }
    else             { src = Wo; dst = g_woh; n = (size_t)EMB * EMB; }

    const size_t stride = (size_t)gridDim.x * blockDim.x * 4;
    for (size_t i = ((size_t)blockIdx.x * blockDim.x + threadIdx.x) * 4;
         i < n; i += stride) {
        float4 v = *reinterpret_cast<const float4*>(src + i);
        __half2* d2 = reinterpret_cast<__half2*>(dst + i);
        d2[0] = __floats2half2_rn(v.x, v.y);
        d2[1] = __floats2half2_rn(v.z, v.w);
    }
}

// ============================================================================
// 4-stage cp.async fp16 GEMM core, ldmatrix loads, WARP TILE 64x64.
// C[M,N] = A[M,K] * B[N,K]^T.  BM=BN=128, BK=32, 128 threads (2x2 warps).
// Compute-first ordering; tail peeled behind wait_group 0.
// ============================================================================
#define GH_BM 128
#define GH_BN 128
#define GH_BK 32
#define GH_S  4
#define GH_THR 128
#define GH_LDT 20
#define GH_TILE (128 * GH_LDT)               // 2560 uints per operand per stage
#define GH_STG  (2 * GH_TILE)
#define GH_SMEM_BYTES (GH_S * GH_STG * 4)    // 81920 B
#define GH_MT 4
#define GH_NT 8

__device__ __forceinline__ void gemm_core_h(
    const __half* __restrict__ A,
    const __half* __restrict__ B,
    int Kdim, int m0, int n0,
    float (&acc)[GH_MT][GH_NT][4])
{
    extern __shared__ uint32_t smh[];
    const uint32_t sm_b = smem_u32(smh);

    const int tid  = threadIdx.x;
    const int lane = tid & 31;
    const int warp = tid >> 5;               // 0..3
    const int wm = (warp >> 1) * 64;         // 2 warp-rows
    const int wn = (warp & 1) * 64;          // 2 warp-cols
    const int mat  = lane >> 3;
    const int rin  = lane & 7;
    const int a_lrow = (mat & 1) * 8 + rin;
    const int a_lcol = (mat >> 1) * 4;
    const int b_sel  = (mat >> 1);
    const int b_lcol = (mat & 1) * 4;

    auto stage = [&](int chunk) {
        const int s = chunk & (GH_S - 1);
        const uint32_t ab = sm_b + (uint32_t)(s * GH_STG) * 4;
        const uint32_t bb = ab + GH_TILE * 4;
        const int k0 = chunk * GH_BK;
        #pragma unroll
        for (int i = 0; i < 4; ++i) {        // 128 rows x 4 cp16 per operand
            int idx = tid + i * GH_THR;
            int row = idx >> 2, q = idx & 3;
            cp16(ab + (uint32_t)(row * GH_LDT + q * 4) * 4,
                 A + (size_t)(m0 + row) * Kdim + k0 + q * 8);
            cp16(bb + (uint32_t)(row * GH_LDT + q * 4) * 4,
                 B + (size_t)(n0 + row) * Kdim + k0 + q * 8);
        }
    };

    auto compute = [&](int i) {
        const uint32_t ab = sm_b + (uint32_t)((i & (GH_S - 1)) * GH_STG) * 4;
        const uint32_t bb = ab + GH_TILE * 4;
        #pragma unroll
        for (int ks = 0; ks < 2; ++ks) {
            uint32_t af[GH_MT][4];
            uint32_t bf[GH_NT][2];
            #pragma unroll
            for (int mt = 0; mt < GH_MT; ++mt) {
                uint32_t ad = ab + (uint32_t)((wm + mt * 16 + a_lrow) * GH_LDT
                                              + ks * 8 + a_lcol) * 4;
                ldsm4(af[mt][0], af[mt][1], af[mt][2], af[mt][3], ad);
            }
            #pragma unroll
            for (int p = 0; p < 4; ++p) {
                uint32_t bd = bb + (uint32_t)((wn + (2 * p + b_sel) * 8 + rin) * GH_LDT
                                              + ks * 8 + b_lcol) * 4;
                ldsm4(bf[2 * p][0], bf[2 * p][1], bf[2 * p + 1][0], bf[2 * p + 1][1], bd);
            }
            #pragma unroll
            for (int mt = 0; mt < GH_MT; ++mt)
                #pragma unroll
                for (int nt = 0; nt < GH_NT; ++nt)
                    mma16(acc[mt][nt], af[mt], bf[nt]);
        }
    };

    const int nchunk = Kdim / GH_BK;
    #pragma unroll
    for (int c = 0; c < GH_S - 1; ++c) {
        stage(c);
        asm volatile("cp.async.commit_group;\n");
    }

    int i = 0;
    for (; i < nchunk - (GH_S - 1); ++i) {
        asm volatile("cp.async.wait_group %0;\n" :: "n"(GH_S - 2));
        __syncthreads();
        compute(i);
        stage(i + GH_S - 1);
        asm volatile("cp.async.commit_group;\n");
    }
    asm volatile("cp.async.wait_group 0;\n");
    __syncthreads();
    for (; i < nchunk; ++i) compute(i);
}

// ---- kernel 1: fused QKV projection (grid.z selects q/k/v) ----
// q,k stored [B,H,S,D]; v stored TRANSPOSED [B,H,D,S] via smem-staged
// coalesced transpose (scattered 2B stores were ~16x write amplification).
#define TR_LDC 136   // halves per c-row in transpose buffer (272 B pitch)

__global__ void __launch_bounds__(GH_THR, 2) qkv_kernel(
    const float* __restrict__ bq, const float* __restrict__ bk,
    const float* __restrict__ bv)
{
    extern __shared__ uint32_t smh[];
    const int z = blockIdx.z;
    const __half* W   = (z == 0) ? g_wqh : ((z == 1) ? g_wkh : g_wvh);
    const float* bptr = (z == 0) ? bq    : ((z == 1) ? bk    : bv);
    __half* out       = (z == 0) ? g_qh  : ((z == 1) ? g_kh  : g_vh);

    float acc[GH_MT][GH_NT][4] = {};
    const int m0 = blockIdx.x * GH_BM, n0 = blockIdx.y * GH_BN;
    gemm_core_h(g_xh, W, EMB, m0, n0, acc);

    const int lane = threadIdx.x & 31, warp = threadIdx.x >> 5;
    const int g = lane >> 2, tg = lane & 3;
    const int wm = (warp >> 1) * 64;
    const int wn = (warp & 1) * 64;

    if (z < 2) {
        #pragma unroll
        for (int mt = 0; mt < GH_MT; ++mt)
            #pragma unroll
            for (int nt = 0; nt < GH_NT; ++nt) {
                int r = m0 + wm + mt * 16 + g;
                int c = n0 + wn + nt * 8 + 2 * tg;       // even
                float v0 = acc[mt][nt][0] + bptr[c];
                float v1 = acc[mt][nt][1] + bptr[c + 1];
                float v2 = acc[mt][nt][2] + bptr[c];
                float v3 = acc[mt][nt][3] + bptr[c + 1];
                int h = c >> 6, d = c & 63;
                int b0 = r >> 10, s0 = r & 1023;
                int b1 = (r + 8) >> 10, s1 = (r + 8) & 1023;
                __half2* p0 = reinterpret_cast<__half2*>(
                    out + (((size_t)b0 * NH + h) * SEQ + s0) * HD + d);
                __half2* p1 = reinterpret_cast<__half2*>(
                    out + (((size_t)b1 * NH + h) * SEQ + s1) * HD + d);
                *p0 = __floats2half2_rn(v0, v1);
                *p1 = __floats2half2_rn(v2, v3);
            }
    } else {
        // V: transpose through smem, then coalesced [B,H,D,S] stores.
        __syncthreads();   // staging smem fully consumed by gemm_core_h
        __half* tsm = reinterpret_cast<__half*>(smh);
        #pragma unroll
        for (int mt = 0; mt < GH_MT; ++mt)
            #pragma unroll
            for (int nt = 0; nt < GH_NT; ++nt) {
                int r  = wm + mt * 16 + g;               // local row (s)
                int cl = wn + nt * 8 + 2 * tg;           // local col (even)
                tsm[(cl    ) * TR_LDC + r    ] = __float2half_rn(acc[mt][nt][0] + bptr[n0 + cl]);
                tsm[(cl + 1) * TR_LDC + r    ] = __float2half_rn(acc[mt][nt][1] + bptr[n0 + cl + 1]);
                tsm[(cl    ) * TR_LDC + r + 8] = __float2half_rn(acc[mt][nt][2] + bptr[n0 + cl]);
                tsm[(cl + 1) * TR_LDC + r + 8] = __float2half_rn(acc[mt][nt][3] + bptr[n0 + cl + 1]);
            }
        __syncthreads();
        const int b0 = m0 >> 10, sbase = m0 & 1023;      // 128-row tile: single b
        #pragma unroll
        for (int i = 0; i < 16; ++i) {
            int pid = threadIdx.x + i * GH_THR;
            int cc = pid >> 4;                           // 0..127 (local col)
            int rc = pid & 15;                           // 8-half chunk of rows
            int cg = n0 + cc;
            int hh = cg >> 6, dd = cg & 63;
            uint4 val = *reinterpret_cast<uint4*>(tsm + cc * TR_LDC + rc * 8);
            *reinterpret_cast<uint4*>(
                out + (((size_t)b0 * NH + hh) * HD + dd) * SEQ + sbase + rc * 8) = val;
        }
    }
}

// ---- kernel 3: out = concat @ Wo^T + bo (fp32 output) ----
__global__ void __launch_bounds__(GH_THR, 2) oproj_kernel(
    const float* __restrict__ bo, float* __restrict__ out)
{
    float acc[GH_MT][GH_NT][4] = {};
    const int m0 = blockIdx.x * GH_BM, n0 = blockIdx.y * GH_BN;
    gemm_core_h(g_oh, g_woh, EMB, m0, n0, acc);

    const int lane = threadIdx.x & 31, warp = threadIdx.x >> 5;
    const int g = lane >> 2, tg = lane & 3;
    const int wm = (warp >> 1) * 64;
    const int wn = (warp & 1) * 64;
    #pragma unroll
    for (int mt = 0; mt < GH_MT; ++mt)
        #pragma unroll
        for (int nt = 0; nt < GH_NT; ++nt) {
            int r = m0 + wm + mt * 16 + g;
            int c = n0 + wn + nt * 8 + 2 * tg;
            out[(size_t)r * EMB + c]           = acc[mt][nt][0] + bo[c];
            out[(size_t)r * EMB + c + 1]       = acc[mt][nt][1] + bo[c + 1];
            out[(size_t)(r + 8) * EMB + c]     = acc[mt][nt][2] + bo[c];
            out[(size_t)(r + 8) * EMB + c + 1] = acc[mt][nt][3] + bo[c + 1];
        }
}

// ============================================================================
// kernel 2: fused flash attention — FA2-style warp-row ownership (unchanged R12)
// ============================================================================
#define FA_BM 128
#define FA_BN 64
#define FA_NT_TILES (SEQ / FA_BN)   // 16
#define FA_LDT 36
#define FA_QS (128 * FA_LDT)
#define FA_KS (64 * FA_LDT)
#define FA_VS (64 * FA_LDT)
#define FA_SMEM_BYTES ((FA_QS + 2 * FA_KS + 2 * FA_VS) * 4)   // 55296 B

__global__ void __launch_bounds__(256, 2) flash_kernel()
{
    extern __shared__ uint32_t fsh[];
    uint32_t* Qu = fsh;
    uint32_t* Ku = Qu + FA_QS;              // [2][64][36]
    uint32_t* Vu = Ku + 2 * FA_KS;          // [2][64][36]
    const uint32_t qu_b = smem_u32(Qu);
    const uint32_t ku_b = smem_u32(Ku);
    const uint32_t vu_b = smem_u32(Vu);

    const int z  = blockIdx.z;
    const int m0 = blockIdx.x * FA_BM;
    const __half* Qh = g_qh + (size_t)z * SEQ * HD;
    const __half* Kh = g_kh + (size_t)z * SEQ * HD;
    const __half* Vh = g_vh + (size_t)z * HD * SEQ;   // [D][S]

    const int tid  = threadIdx.x;
    const int lane = tid & 31, warp = tid >> 5;
    const int g = lane >> 2, tg = lane & 3;
    const int mat  = lane >> 3, rin = lane & 7;
    const int a_lrow = (mat & 1) * 8 + rin;
    const int a_lcol = (mat >> 1) * 4;
    const int b_sel  = (mat >> 1);
    const int b_lcol = (mat & 1) * 4;
    const int wrow = warp * 16;             // this warp's 16 rows

    auto stage_kv = [&](int t) {
        const uint32_t kb = ku_b + (uint32_t)((t & 1) * FA_KS) * 4;
        const uint32_t vb = vu_b + (uint32_t)((t & 1) * FA_VS) * 4;
        const int n0 = t * FA_BN;
        #pragma unroll
        for (int i = 0; i < 2; ++i) {
            int idx = tid + i * 256;
            int rr = idx >> 3, q = idx & 7;
            cp16(kb + (uint32_t)(rr * FA_LDT + q * 4) * 4,
                 Kh + (size_t)(n0 + rr) * HD + q * 8);
            cp16(vb + (uint32_t)(rr * FA_LDT + q * 4) * 4,
                 Vh + (size_t)rr * SEQ + n0 + q * 8);
        }
    };

    // stage Q + tile 0
    #pragma unroll
    for (int i = 0; i < 4; ++i) {
        int idx = tid + i * 256;
        int r = idx >> 3, q = idx & 7;
        cp16(qu_b + (uint32_t)(r * FA_LDT + q * 4) * 4,
             Qh + (size_t)(m0 + r) * HD + q * 8);
    }
    stage_kv(0);
    asm volatile("cp.async.commit_group;\n");

    float acc_o[8][4] = {};
    float m_st[2] = {-1e30f, -1e30f};
    float l_st[2] = {0.f, 0.f};

    for (int t = 0; t < FA_NT_TILES; ++t) {
        __syncthreads();   // all warps done reading buf (t+1)&1 from iter t-1

        if (t + 1 < FA_NT_TILES) {
            stage_kv(t + 1);
            asm volatile("cp.async.commit_group;\n");
            asm volatile("cp.async.wait_group 1;\n");   // tile t arrived
        } else {
            asm volatile("cp.async.wait_group 0;\n");
        }
        __syncthreads();   // tile t visible to all warps

        const uint32_t kub = ku_b + (uint32_t)((t & 1) * FA_KS) * 4;
        const uint32_t vub = vu_b + (uint32_t)((t & 1) * FA_VS) * 4;

        // ---- S = Q_w (16x64) K^T ----
        float acc_s[8][4] = {};
        #pragma unroll
        for (int ks = 0; ks < 4; ++ks) {
            uint32_t af[4];
            uint32_t bf[8][2];
            uint32_t ad = qu_b + (uint32_t)((wrow + a_lrow) * FA_LDT
                                            + ks * 8 + a_lcol) * 4;
            ldsm4(af[0], af[1], af[2], af[3], ad);
            #pragma unroll
            for (int p = 0; p < 4; ++p) {
                uint32_t bd = kub + (uint32_t)(((2 * p + b_sel) * 8 + rin) * FA_LDT
                                               + ks * 8 + b_lcol) * 4;
                ldsm4(bf[2 * p][0], bf[2 * p][1], bf[2 * p + 1][0], bf[2 * p + 1][1], bd);
            }
            #pragma unroll
            for (int nt = 0; nt < 8; ++nt)
                mma16(acc_s[nt], af, bf[nt]);
        }
        #pragma unroll
        for (int nt = 0; nt < 8; ++nt)
            #pragma unroll
            for (int e = 0; e < 4; ++e)
                acc_s[nt][e] *= 0.125f;

        // ---- warp-local online softmax; P packed into registers ----
        uint32_t plo[8], phi[8];
        #pragma unroll
        for (int h = 0; h < 2; ++h) {
            float m = -1e30f;
            #pragma unroll
            for (int nt = 0; nt < 8; ++nt)
                m = fmaxf(m, fmaxf(acc_s[nt][2 * h], acc_s[nt][2 * h + 1]));
            m = fmaxf(m, __shfl_xor_sync(0xffffffffu, m, 1));
            m = fmaxf(m, __shfl_xor_sync(0xffffffffu, m, 2));
            float mnew = fmaxf(m_st[h], m);
            float sc = __expf(m_st[h] - mnew);
            m_st[h] = mnew;
            l_st[h] *= sc;
            #pragma unroll
            for (int nt = 0; nt < 8; ++nt) {
                acc_o[nt][2 * h]     *= sc;
                acc_o[nt][2 * h + 1] *= sc;
            }
            float rs = 0.f;
            #pragma unroll
            for (int nt = 0; nt < 8; ++nt) {
                float p0 = __expf(acc_s[nt][2 * h]     - mnew);
                float p1 = __expf(acc_s[nt][2 * h + 1] - mnew);
                rs += p0 + p1;
                uint32_t pk = h2_bits(__floats2half2_rn(p0, p1));
                if (h == 0) plo[nt] = pk; else phi[nt] = pk;
            }
            rs += __shfl_xor_sync(0xffffffffu, rs, 1);
            rs += __shfl_xor_sync(0xffffffffu, rs, 2);
            l_st[h] += rs;
        }

        // ---- O += P V : P A-fragments straight from registers ----
        #pragma unroll
        for (int ks = 0; ks < 4; ++ks) {
            uint32_t af[4] = { plo[2 * ks], phi[2 * ks],
                               plo[2 * ks + 1], phi[2 * ks + 1] };
            uint32_t bf[8][2];
            #pragma unroll
            for (int p = 0; p < 4; ++p) {
                uint32_t bd = vub + (uint32_t)(((2 * p + b_sel) * 8 + rin) * FA_LDT
                                               + ks * 8 + b_lcol) * 4;
                ldsm4(bf[2 * p][0], bf[2 * p][1], bf[2 * p + 1][0], bf[2 * p + 1][1], bd);
            }
            #pragma unroll
            for (int nt = 0; nt < 8; ++nt)
                mma16(acc_o[nt], af, bf[nt]);
        }
    }

    // ---- epilogue: O /= l, half2 stores into concat layout [B,S,H*D] ----
    const int b = z >> 4, h = z & 15;
    const float inv0 = 1.0f / l_st[0];
    const float inv1 = 1.0f / l_st[1];
    const int s0 = m0 + wrow + g;
    #pragma unroll
    for (int nt = 0; nt < 8; ++nt) {
        int d0 = nt * 8 + 2 * tg;               // even
        size_t base0 = ((size_t)(b * SEQ + s0)) * EMB + h * HD + d0;
        size_t base1 = ((size_t)(b * SEQ + s0 + 8)) * EMB + h * HD + d0;
        *reinterpret_cast<__half2*>(g_oh + base0) =
            __floats2half2_rn(acc_o[nt][0] * inv0, acc_o[nt][1] * inv0);
        *reinterpret_cast<__half2*>(g_oh + base1) =
            __floats2half2_rn(acc_o[nt][2] * inv1, acc_o[nt][3] * inv1);
    }
}

extern "C" void kernel_launch(void* const* d_in, const int* in_sizes, int n_in,
                              void* d_out, int out_size)
{
    const float* x  = (const float*)d_in[0];
    const float* Wq = (const float*)d_in[1];
    const float* bq = (const float*)d_in[2];
    const float* Wk = (const float*)d_in[3];
    const float* bk = (const float*)d_in[4];
    const float* Wv = (const float*)d_in[5];
    const float* bv = (const float*)d_in[6];
    const float* Wo = (const float*)d_in[7];
    const float* bo = (const float*)d_in[8];
    float* out = (float*)d_out;

    cudaFuncSetAttribute(qkv_kernel,
                         cudaFuncAttributeMaxDynamicSharedMemorySize, GH_SMEM_BYTES);
    cudaFuncSetAttribute(oproj_kernel,
                         cudaFuncAttributeMaxDynamicSharedMemorySize, GH_SMEM_BYTES);
    cudaFuncSetAttribute(flash_kernel,
                         cudaFuncAttributeMaxDynamicSharedMemorySize, FA_SMEM_BYTES);

    convert_kernel<<<dim3(1024, 1, 5), 256>>>(x, Wq, Wk, Wv, Wo);
    qkv_kernel<<<dim3(MROWS / GH_BM, EMB / GH_BN, 3), GH_THR, GH_SMEM_BYTES>>>(bq, bk, bv);
    flash_kernel<<<dim3(SEQ / FA_BM, 1, BH), 256, FA_SMEM_BYTES>>>();
    oproj_kernel<<<dim3(MROWS / GH_BM, EMB / GH_BN, 1), GH_THR, GH_SMEM_BYTES>>>(bo, out);
}

// round 15
// speedup vs baseline: 1.1558x; 1.0332x over previous
#include <cuda_runtime.h>
#include <cuda_fp16.h>
#include <cstdint>
#include <cstddef>

#define BATCH 4
#define SEQ   1024
#define EMB   1024
#define NH    16
#define HD    64
#define BH    (BATCH * NH)      // 64
#define MROWS (BATCH * SEQ)     // 4096

// ---- scratch (device globals: allocation-free per harness rules) ----
__device__ __half g_xh[(size_t)MROWS * EMB];          // rounded x (8 MB)
__device__ __half g_wqh[(size_t)EMB * EMB];           // 2 MB each
__device__ __half g_wkh[(size_t)EMB * EMB];
__device__ __half g_wvh[(size_t)EMB * EMB];
__device__ __half g_woh[(size_t)EMB * EMB];
__device__ __half g_qh[(size_t)BH * SEQ * HD];        // [B,H,S,D]
__device__ __half g_kh[(size_t)BH * SEQ * HD];        // [B,H,S,D]
__device__ __half g_vh[(size_t)BH * SEQ * HD];        // [B,H,D,S]  (TRANSPOSED)
__device__ __half g_oh[(size_t)MROWS * EMB];          // [B,S,H*D] concat

// fp16 mma m16n8k16, fp32 accumulate
__device__ __forceinline__ void mma16(float* c, const uint32_t* a, const uint32_t* b) {
    asm volatile(
        "mma.sync.aligned.m16n8k16.row.col.f32.f16.f16.f32 "
        "{%0,%1,%2,%3}, {%4,%5,%6,%7}, {%8,%9}, {%0,%1,%2,%3};\n"
        : "+f"(c[0]), "+f"(c[1]), "+f"(c[2]), "+f"(c[3])
        : "r"(a[0]), "r"(a[1]), "r"(a[2]), "r"(a[3]),
          "r"(b[0]), "r"(b[1]));
}

__device__ __forceinline__ void cp16(uint32_t dst, const void* src) {
    asm volatile("cp.async.cg.shared.global [%0], [%1], 16;\n"
                 :: "r"(dst), "l"(src));
}

__device__ __forceinline__ void ldsm4(uint32_t& r0, uint32_t& r1,
                                      uint32_t& r2, uint32_t& r3, uint32_t addr) {
    asm volatile("ldmatrix.sync.aligned.m8n8.x4.shared.b16 {%0,%1,%2,%3}, [%4];"
                 : "=r"(r0), "=r"(r1), "=r"(r2), "=r"(r3) : "r"(addr));
}

__device__ __forceinline__ uint32_t smem_u32(const void* p) {
    uint32_t a;
    asm("{ .reg .u64 t; cvta.to.shared.u64 t, %1; cvt.u32.u64 %0, t; }"
        : "=r"(a) : "l"(p));
    return a;
}

__device__ __forceinline__ uint32_t h2_bits(__half2 h) {
    return *reinterpret_cast<uint32_t*>(&h);
}

// ---- kernel 0: convert inputs to fp16 in scratch ----
__global__ void __launch_bounds__(256) convert_kernel(
    const float* __restrict__ x,
    const float* __restrict__ Wq, const float* __restrict__ Wk,
    const float* __restrict__ Wv, const float* __restrict__ Wo)
{
    const int z = blockIdx.z;
    const float* src;
    __half* dst;
    size_t n;
    if (z == 0)      { src = x;  dst = g_xh;  n = (size_t)MROWS * EMB; }
    else if (z == 1) { src = Wq; dst = g_wqh; n = (size_t)EMB * EMB; }
    else if (z == 2) { src = Wk; dst = g_wkh; n = (size_t)EMB * EMB; }
    else if (z == 3) { src = Wv; dst = g_wvh; n = (size_t)EMB * EMB; }
    else             { src = Wo; dst = g_woh; n = (size_t)EMB * EMB; }

    const size_t stride = (size_t)gridDim.x * blockDim.x * 4;
    for (size_t i = ((size_t)blockIdx.x * blockDim.x + threadIdx.x) * 4;
         i < n; i += stride) {
        float4 v = *reinterpret_cast<const float4*>(src + i);
        __half2* d2 = reinterpret_cast<__half2*>(dst + i);
        d2[0] = __floats2half2_rn(v.x, v.y);
        d2[1] = __floats2half2_rn(v.z, v.w);
    }
}

// ============================================================================
// 3-stage cp.async fp16 GEMM core, BK=64 (half the barriers of BK=32),
// ldmatrix loads, warp tile 64x64, 128 threads (2x2 warps).
// C[M,N] = A[M,K] * B[N,K]^T.  Same k-order as BK=32 -> bit-identical.
// ============================================================================
#define GH_BM 128
#define GH_BN 128
#define GH_BK 64
#define GH_S  3
#define GH_THR 128
#define GH_LDT 36                            // 32 data uints + 4 pad (64 halves)
#define GH_TILE (128 * GH_LDT)               // 4608 uints per operand per stage
#define GH_STG  (2 * GH_TILE)
#define GH_SMEM_BYTES (GH_S * GH_STG * 4)    // 110592 B
#define GH_MT 4
#define GH_NT 8

__device__ __forceinline__ void gemm_core_h(
    const __half* __restrict__ A,
    const __half* __restrict__ B,
    int Kdim, int m0, int n0,
    float (&acc)[GH_MT][GH_NT][4])
{
    extern __shared__ uint32_t smh[];
    const uint32_t sm_b = smem_u32(smh);

    const int tid  = threadIdx.x;
    const int lane = tid & 31;
    const int warp = tid >> 5;               // 0..3
    const int wm = (warp >> 1) * 64;         // 2 warp-rows
    const int wn = (warp & 1) * 64;          // 2 warp-cols
    const int mat  = lane >> 3;
    const int rin  = lane & 7;
    const int a_lrow = (mat & 1) * 8 + rin;
    const int a_lcol = (mat >> 1) * 4;
    const int b_sel  = (mat >> 1);
    const int b_lcol = (mat & 1) * 4;

    auto stage = [&](int chunk) {
        const int s = chunk % GH_S;
        const uint32_t ab = sm_b + (uint32_t)(s * GH_STG) * 4;
        const uint32_t bb = ab + GH_TILE * 4;
        const int k0 = chunk * GH_BK;
        #pragma unroll
        for (int i = 0; i < 8; ++i) {        // 128 rows x 8 cp16 per operand
            int idx = tid + i * GH_THR;
            int row = idx >> 3, q = idx & 7;
            cp16(ab + (uint32_t)(row * GH_LDT + q * 4) * 4,
                 A + (size_t)(m0 + row) * Kdim + k0 + q * 8);
            cp16(bb + (uint32_t)(row * GH_LDT + q * 4) * 4,
                 B + (size_t)(n0 + row) * Kdim + k0 + q * 8);
        }
    };

    auto compute = [&](int i) {
        const uint32_t ab = sm_b + (uint32_t)((i % GH_S) * GH_STG) * 4;
        const uint32_t bb = ab + GH_TILE * 4;
        #pragma unroll
        for (int ks = 0; ks < 4; ++ks) {     // 4 k16 steps per BK=64 chunk
            uint32_t af[GH_MT][4];
            uint32_t bf[GH_NT][2];
            #pragma unroll
            for (int mt = 0; mt < GH_MT; ++mt) {
                uint32_t ad = ab + (uint32_t)((wm + mt * 16 + a_lrow) * GH_LDT
                                              + ks * 8 + a_lcol) * 4;
                ldsm4(af[mt][0], af[mt][1], af[mt][2], af[mt][3], ad);
            }
            #pragma unroll
            for (int p = 0; p < 4; ++p) {
                uint32_t bd = bb + (uint32_t)((wn + (2 * p + b_sel) * 8 + rin) * GH_LDT
                                              + ks * 8 + b_lcol) * 4;
                ldsm4(bf[2 * p][0], bf[2 * p][1], bf[2 * p + 1][0], bf[2 * p + 1][1], bd);
            }
            #pragma unroll
            for (int mt = 0; mt < GH_MT; ++mt)
                #pragma unroll
                for (int nt = 0; nt < GH_NT; ++nt)
                    mma16(acc[mt][nt], af[mt], bf[nt]);
        }
    };

    const int nchunk = Kdim / GH_BK;         // 16
    #pragma unroll
    for (int c = 0; c < GH_S - 1; ++c) {
        stage(c);
        asm volatile("cp.async.commit_group;\n");
    }

    int i = 0;
    for (; i < nchunk - (GH_S - 1); ++i) {
        asm volatile("cp.async.wait_group %0;\n" :: "n"(GH_S - 2));
        __syncthreads();
        compute(i);
        stage(i + GH_S - 1);
        asm volatile("cp.async.commit_group;\n");
    }
    asm volatile("cp.async.wait_group 0;\n");
    __syncthreads();
    for (; i < nchunk; ++i) compute(i);
}

// ---- kernel 1: fused QKV projection (grid.z selects q/k/v) ----
// q,k stored [B,H,S,D]; v stored TRANSPOSED [B,H,D,S] via smem-staged
// coalesced transpose.
#define TR_LDC 136   // halves per c-row in transpose buffer (272 B pitch)

__global__ void __launch_bounds__(GH_THR, 2) qkv_kernel(
    const float* __restrict__ bq, const float* __restrict__ bk,
    const float* __restrict__ bv)
{
    extern __shared__ uint32_t smh[];
    const int z = blockIdx.z;
    const __half* W   = (z == 0) ? g_wqh : ((z == 1) ? g_wkh : g_wvh);
    const float* bptr = (z == 0) ? bq    : ((z == 1) ? bk    : bv);
    __half* out       = (z == 0) ? g_qh  : ((z == 1) ? g_kh  : g_vh);

    float acc[GH_MT][GH_NT][4] = {};
    const int m0 = blockIdx.x * GH_BM, n0 = blockIdx.y * GH_BN;
    gemm_core_h(g_xh, W, EMB, m0, n0, acc);

    const int lane = threadIdx.x & 31, warp = threadIdx.x >> 5;
    const int g = lane >> 2, tg = lane & 3;
    const int wm = (warp >> 1) * 64;
    const int wn = (warp & 1) * 64;

    if (z < 2) {
        #pragma unroll
        for (int mt = 0; mt < GH_MT; ++mt)
            #pragma unroll
            for (int nt = 0; nt < GH_NT; ++nt) {
                int r = m0 + wm + mt * 16 + g;
                int c = n0 + wn + nt * 8 + 2 * tg;       // even
                float v0 = acc[mt][nt][0] + bptr[c];
                float v1 = acc[mt][nt][1] + bptr[c + 1];
                float v2 = acc[mt][nt][2] + bptr[c];
                float v3 = acc[mt][nt][3] + bptr[c + 1];
                int h = c >> 6, d = c & 63;
                int b0 = r >> 10, s0 = r & 1023;
                int b1 = (r + 8) >> 10, s1 = (r + 8) & 1023;
                __half2* p0 = reinterpret_cast<__half2*>(
                    out + (((size_t)b0 * NH + h) * SEQ + s0) * HD + d);
                __half2* p1 = reinterpret_cast<__half2*>(
                    out + (((size_t)b1 * NH + h) * SEQ + s1) * HD + d);
                *p0 = __floats2half2_rn(v0, v1);
                *p1 = __floats2half2_rn(v2, v3);
            }
    } else {
        // V: transpose through smem, then coalesced [B,H,D,S] stores.
        __syncthreads();   // staging smem fully consumed by gemm_core_h
        __half* tsm = reinterpret_cast<__half*>(smh);
        #pragma unroll
        for (int mt = 0; mt < GH_MT; ++mt)
            #pragma unroll
            for (int nt = 0; nt < GH_NT; ++nt) {
                int r  = wm + mt * 16 + g;               // local row (s)
                int cl = wn + nt * 8 + 2 * tg;           // local col (even)
                tsm[(cl    ) * TR_LDC + r    ] = __float2half_rn(acc[mt][nt][0] + bptr[n0 + cl]);
                tsm[(cl + 1) * TR_LDC + r    ] = __float2half_rn(acc[mt][nt][1] + bptr[n0 + cl + 1]);
                tsm[(cl    ) * TR_LDC + r + 8] = __float2half_rn(acc[mt][nt][2] + bptr[n0 + cl]);
                tsm[(cl + 1) * TR_LDC + r + 8] = __float2half_rn(acc[mt][nt][3] + bptr[n0 + cl + 1]);
            }
        __syncthreads();
        const int b0 = m0 >> 10, sbase = m0 & 1023;      // 128-row tile: single b
        #pragma unroll
        for (int i = 0; i < 16; ++i) {
            int pid = threadIdx.x + i * GH_THR;
            int cc = pid >> 4;                           // 0..127 (local col)
            int rc = pid & 15;                           // 8-half chunk of rows
            int cg = n0 + cc;
            int hh = cg >> 6, dd = cg & 63;
            uint4 val = *reinterpret_cast<uint4*>(tsm + cc * TR_LDC + rc * 8);
            *reinterpret_cast<uint4*>(
                out + (((size_t)b0 * NH + hh) * HD + dd) * SEQ + sbase + rc * 8) = val;
        }
    }
}

// ---- kernel 3: out = concat @ Wo^T + bo (fp32 output) ----
__global__ void __launch_bounds__(GH_THR, 2) oproj_kernel(
    const float* __restrict__ bo, float* __restrict__ out)
{
    float acc[GH_MT][GH_NT][4] = {};
    const int m0 = blockIdx.x * GH_BM, n0 = blockIdx.y * GH_BN;
    gemm_core_h(g_oh, g_woh, EMB, m0, n0, acc);

    const int lane = threadIdx.x & 31, warp = threadIdx.x >> 5;
    const int g = lane >> 2, tg = lane & 3;
    const int wm = (warp >> 1) * 64;
    const int wn = (warp & 1) * 64;
    #pragma unroll
    for (int mt = 0; mt < GH_MT; ++mt)
        #pragma unroll
        for (int nt = 0; nt < GH_NT; ++nt) {
            int r = m0 + wm + mt * 16 + g;
            int c = n0 + wn + nt * 8 + 2 * tg;
            out[(size_t)r * EMB + c]           = acc[mt][nt][0] + bo[c];
            out[(size_t)r * EMB + c + 1]       = acc[mt][nt][1] + bo[c + 1];
            out[(size_t)(r + 8) * EMB + c]     = acc[mt][nt][2] + bo[c];
            out[(size_t)(r + 8) * EMB + c + 1] = acc[mt][nt][3] + bo[c + 1];
        }
}

// ============================================================================
// kernel 2: fused flash attention — FA2 warp-row ownership, K/V RING-3 with
// ONE barrier per tile. Safety: all warps past top-of-iter-t barrier finished
// compute(t-1); stage(t+2) at iter-t end writes buf (t+2)%3 == (t-1)%3 which
// nothing reads anymore; per-thread wait_group 1 before the barrier ensures
// tile t complete, barrier makes it visible.
// ============================================================================
#define FA_BM 128
#define FA_BN 64
#define FA_NT_TILES (SEQ / FA_BN)   // 16
#define FA_LDT 36
#define FA_QS (128 * FA_LDT)
#define FA_KS (64 * FA_LDT)
#define FA_VS (64 * FA_LDT)
#define FA_SMEM_BYTES ((FA_QS + 3 * FA_KS + 3 * FA_VS) * 4)   // 73728 B

__global__ void __launch_bounds__(256, 2) flash_kernel()
{
    extern __shared__ uint32_t fsh[];
    uint32_t* Qu = fsh;
    uint32_t* Ku = Qu + FA_QS;              // [3][64][36]
    uint32_t* Vu = Ku + 3 * FA_KS;          // [3][64][36]
    const uint32_t qu_b = smem_u32(Qu);
    const uint32_t ku_b = smem_u32(Ku);
    const uint32_t vu_b = smem_u32(Vu);

    const int z  = blockIdx.z;
    const int m0 = blockIdx.x * FA_BM;
    const __half* Qh = g_qh + (size_t)z * SEQ * HD;
    const __half* Kh = g_kh + (size_t)z * SEQ * HD;
    const __half* Vh = g_vh + (size_t)z * HD * SEQ;   // [D][S]

    const int tid  = threadIdx.x;
    const int lane = tid & 31, warp = tid >> 5;
    const int g = lane >> 2, tg = lane & 3;
    const int mat  = lane >> 3, rin = lane & 7;
    const int a_lrow = (mat & 1) * 8 + rin;
    const int a_lcol = (mat >> 1) * 4;
    const int b_sel  = (mat >> 1);
    const int b_lcol = (mat & 1) * 4;
    const int wrow = warp * 16;             // this warp's 16 rows

    auto stage_kv = [&](int t) {
        const int s = t % 3;
        const uint32_t kb = ku_b + (uint32_t)(s * FA_KS) * 4;
        const uint32_t vb = vu_b + (uint32_t)(s * FA_VS) * 4;
        const int n0 = t * FA_BN;
        #pragma unroll
        for (int i = 0; i < 2; ++i) {
            int idx = tid + i * 256;
            int rr = idx >> 3, q = idx & 7;
            cp16(kb + (uint32_t)(rr * FA_LDT + q * 4) * 4,
                 Kh + (size_t)(n0 + rr) * HD + q * 8);
            cp16(vb + (uint32_t)(rr * FA_LDT + q * 4) * 4,
                 Vh + (size_t)rr * SEQ + n0 + q * 8);
        }
    };

    // prologue: Q + tile 0 (group), tile 1 (group)
    #pragma unroll
    for (int i = 0; i < 4; ++i) {
        int idx = tid + i * 256;
        int r = idx >> 3, q = idx & 7;
        cp16(qu_b + (uint32_t)(r * FA_LDT + q * 4) * 4,
             Qh + (size_t)(m0 + r) * HD + q * 8);
    }
    stage_kv(0);
    asm volatile("cp.async.commit_group;\n");
    stage_kv(1);
    asm volatile("cp.async.commit_group;\n");

    float acc_o[8][4] = {};
    float m_st[2] = {-1e30f, -1e30f};
    float l_st[2] = {0.f, 0.f};

    for (int t = 0; t < FA_NT_TILES; ++t) {
        // tile t complete (per-thread), then single barrier for visibility +
        // "all warps done with iter t-1" (which frees buf (t+2)%3 for staging)
        if (t + 1 < FA_NT_TILES) {
            asm volatile("cp.async.wait_group 1;\n");
        } else {
            asm volatile("cp.async.wait_group 0;\n");
        }
        __syncthreads();

        const int s = t % 3;
        const uint32_t kub = ku_b + (uint32_t)(s * FA_KS) * 4;
        const uint32_t vub = vu_b + (uint32_t)(s * FA_VS) * 4;

        // ---- S = Q_w (16x64) K^T ----
        float acc_s[8][4] = {};
        #pragma unroll
        for (int ks = 0; ks < 4; ++ks) {
            uint32_t af[4];
            uint32_t bf[8][2];
            uint32_t ad = qu_b + (uint32_t)((wrow + a_lrow) * FA_LDT
                                            + ks * 8 + a_lcol) * 4;
            ldsm4(af[0], af[1], af[2], af[3], ad);
            #pragma unroll
            for (int p = 0; p < 4; ++p) {
                uint32_t bd = kub + (uint32_t)(((2 * p + b_sel) * 8 + rin) * FA_LDT
                                               + ks * 8 + b_lcol) * 4;
                ldsm4(bf[2 * p][0], bf[2 * p][1], bf[2 * p + 1][0], bf[2 * p + 1][1], bd);
            }
            #pragma unroll
            for (int nt = 0; nt < 8; ++nt)
                mma16(acc_s[nt], af, bf[nt]);
        }
        #pragma unroll
        for (int nt = 0; nt < 8; ++nt)
            #pragma unroll
            for (int e = 0; e < 4; ++e)
                acc_s[nt][e] *= 0.125f;

        // ---- warp-local online softmax; P packed into registers ----
        uint32_t plo[8], phi[8];
        #pragma unroll
        for (int h = 0; h < 2; ++h) {
            float m = -1e30f;
            #pragma unroll
            for (int nt = 0; nt < 8; ++nt)
                m = fmaxf(m, fmaxf(acc_s[nt][2 * h], acc_s[nt][2 * h + 1]));
            m = fmaxf(m, __shfl_xor_sync(0xffffffffu, m, 1));
            m = fmaxf(m, __shfl_xor_sync(0xffffffffu, m, 2));
            float mnew = fmaxf(m_st[h], m);
            float sc = __expf(m_st[h] - mnew);
            m_st[h] = mnew;
            l_st[h] *= sc;
            #pragma unroll
            for (int nt = 0; nt < 8; ++nt) {
                acc_o[nt][2 * h]     *= sc;
                acc_o[nt][2 * h + 1] *= sc;
            }
            float rs = 0.f;
            #pragma unroll
            for (int nt = 0; nt < 8; ++nt) {
                float p0 = __expf(acc_s[nt][2 * h]     - mnew);
                float p1 = __expf(acc_s[nt][2 * h + 1] - mnew);
                rs += p0 + p1;
                uint32_t pk = h2_bits(__floats2half2_rn(p0, p1));
                if (h == 0) plo[nt] = pk; else phi[nt] = pk;
            }
            rs += __shfl_xor_sync(0xffffffffu, rs, 1);
            rs += __shfl_xor_sync(0xffffffffu, rs, 2);
            l_st[h] += rs;
        }

        // ---- O += P V : P A-fragments straight from registers ----
        #pragma unroll
        for (int ks = 0; ks < 4; ++ks) {
            uint32_t af[4] = { plo[2 * ks], phi[2 * ks],
                               plo[2 * ks + 1], phi[2 * ks + 1] };
            uint32_t bf[8][2];
            #pragma unroll
            for (int p = 0; p < 4; ++p) {
                uint32_t bd = vub + (uint32_t)(((2 * p + b_sel) * 8 + rin) * FA_LDT
                                               + ks * 8 + b_lcol) * 4;
                ldsm4(bf[2 * p][0], bf[2 * p][1], bf[2 * p + 1][0], bf[2 * p + 1][1], bd);
            }
            #pragma unroll
            for (int nt = 0; nt < 8; ++nt)
                mma16(acc_o[nt], af, bf[nt]);
        }

        // stage tile t+2 into buf (t+2)%3 (freed by this iter's barrier)
        if (t + 2 < FA_NT_TILES) {
            stage_kv(t + 2);
            asm volatile("cp.async.commit_group;\n");
        }
    }

    // ---- epilogue: O /= l, half2 stores into concat layout [B,S,H*D] ----
    const int b = z >> 4, h = z & 15;
    const float inv0 = 1.0f / l_st[0];
    const float inv1 = 1.0f / l_st[1];
    const int s0 = m0 + wrow + g;
    #pragma unroll
    for (int nt = 0; nt < 8; ++nt) {
        int d0 = nt * 8 + 2 * tg;               // even
        size_t base0 = ((size_t)(b * SEQ + s0)) * EMB + h * HD + d0;
        size_t base1 = ((size_t)(b * SEQ + s0 + 8)) * EMB + h * HD + d0;
        *reinterpret_cast<__half2*>(g_oh + base0) =
            __floats2half2_rn(acc_o[nt][0] * inv0, acc_o[nt][1] * inv0);
        *reinterpret_cast<__half2*>(g_oh + base1) =
            __floats2half2_rn(acc_o[nt][2] * inv1, acc_o[nt][3] * inv1);
    }
}

extern "C" void kernel_launch(void* const* d_in, const int* in_sizes, int n_in,
                              void* d_out, int out_size)
{
    const float* x  = (const float*)d_in[0];
    const float* Wq = (const float*)d_in[1];
    const float* bq = (const float*)d_in[2];
    const float* Wk = (const float*)d_in[3];
    const float* bk = (const float*)d_in[4];
    const float* Wv = (const float*)d_in[5];
    const float* bv = (const float*)d_in[6];
    const float* Wo = (const float*)d_in[7];
    const float* bo = (const float*)d_in[8];
    float* out = (float*)d_out;

    cudaFuncSetAttribute(qkv_kernel,
                         cudaFuncAttributeMaxDynamicSharedMemorySize, GH_SMEM_BYTES);
    cudaFuncSetAttribute(oproj_kernel,
                         cudaFuncAttributeMaxDynamicSharedMemorySize, GH_SMEM_BYTES);
    cudaFuncSetAttribute(flash_kernel,
                         cudaFuncAttributeMaxDynamicSharedMemorySize, FA_SMEM_BYTES);

    convert_kernel<<<dim3(1024, 1, 5), 256>>>(x, Wq, Wk, Wv, Wo);
    qkv_kernel<<<dim3(MROWS / GH_BM, EMB / GH_BN, 3), GH_THR, GH_SMEM_BYTES>>>(bq, bk, bv);
    flash_kernel<<<dim3(SEQ / FA_BM, 1, BH), 256, FA_SMEM_BYTES>>>();
    oproj_kernel<<<dim3(MROWS / GH_BM, EMB / GH_BN, 1), GH_THR, GH_SMEM_BYTES>>>(bo, out);
}

// round 16
// speedup vs baseline: 1.1817x; 1.0224x over previous
#include <cuda_runtime.h>
#include <cuda_fp16.h>
#include <cstdint>
#include <cstddef>

#define BATCH 4
#define SEQ   1024
#define EMB   1024
#define NH    16
#define HD    64
#define BH    (BATCH * NH)      // 64
#define MROWS (BATCH * SEQ)     // 4096

// ---- scratch (device globals: allocation-free per harness rules) ----
__device__ __half g_xh[(size_t)MROWS * EMB];          // rounded x (8 MB)
__device__ __half g_wqh[(size_t)EMB * EMB];           // 2 MB each
__device__ __half g_wkh[(size_t)EMB * EMB];
__device__ __half g_wvh[(size_t)EMB * EMB];
__device__ __half g_woh[(size_t)EMB * EMB];
__device__ __half g_qh[(size_t)BH * SEQ * HD];        // [B,H,S,D]
__device__ __half g_kh[(size_t)BH * SEQ * HD];        // [B,H,S,D]
__device__ __half g_vh[(size_t)BH * SEQ * HD];        // [B,H,D,S]  (TRANSPOSED)
__device__ __half g_oh[(size_t)MROWS * EMB];          // [B,S,H*D] concat

// fp16 mma m16n8k16, fp32 accumulate
__device__ __forceinline__ void mma16(float* c, const uint32_t* a, const uint32_t* b) {
    asm volatile(
        "mma.sync.aligned.m16n8k16.row.col.f32.f16.f16.f32 "
        "{%0,%1,%2,%3}, {%4,%5,%6,%7}, {%8,%9}, {%0,%1,%2,%3};\n"
        : "+f"(c[0]), "+f"(c[1]), "+f"(c[2]), "+f"(c[3])
        : "r"(a[0]), "r"(a[1]), "r"(a[2]), "r"(a[3]),
          "r"(b[0]), "r"(b[1]));
}

__device__ __forceinline__ void cp16(uint32_t dst, const void* src) {
    asm volatile("cp.async.cg.shared.global [%0], [%1], 16;\n"
                 :: "r"(dst), "l"(src));
}

__device__ __forceinline__ void ldsm4(uint32_t& r0, uint32_t& r1,
                                      uint32_t& r2, uint32_t& r3, uint32_t addr) {
    asm volatile("ldmatrix.sync.aligned.m8n8.x4.shared.b16 {%0,%1,%2,%3}, [%4];"
                 : "=r"(r0), "=r"(r1), "=r"(r2), "=r"(r3) : "r"(addr));
}

__device__ __forceinline__ uint32_t smem_u32(const void* p) {
    uint32_t a;
    asm("{ .reg .u64 t; cvta.to.shared.u64 t, %1; cvt.u32.u64 %0, t; }"
        : "=r"(a) : "l"(p));
    return a;
}

__device__ __forceinline__ uint32_t h2_bits(__half2 h) {
    return *reinterpret_cast<uint32_t*>(&h);
}

// ---- kernel 0: convert inputs to fp16 (8 elems/thread, 16B stores) ----
__global__ void __launch_bounds__(256) convert_kernel(
    const float* __restrict__ x,
    const float* __restrict__ Wq, const float* __restrict__ Wk,
    const float* __restrict__ Wv, const float* __restrict__ Wo)
{
    const int z = blockIdx.z;
    const float* src;
    __half* dst;
    size_t n;
    if (z == 0)      { src = x;  dst = g_xh;  n = (size_t)MROWS * EMB; }
    else if (z == 1) { src = Wq; dst = g_wqh; n = (size_t)EMB * EMB; }
    else if (z == 2) { src = Wk; dst = g_wkh; n = (size_t)EMB * EMB; }
    else if (z == 3) { src = Wv; dst = g_wvh; n = (size_t)EMB * EMB; }
    else             { src = Wo; dst = g_woh; n = (size_t)EMB * EMB; }

    const size_t stride = (size_t)gridDim.x * blockDim.x * 8;
    for (size_t i = ((size_t)blockIdx.x * blockDim.x + threadIdx.x) * 8;
         i < n; i += stride) {
        float4 v0 = *reinterpret_cast<const float4*>(src + i);
        float4 v1 = *reinterpret_cast<const float4*>(src + i + 4);
        __half2 h[4];
        h[0] = __floats2half2_rn(v0.x, v0.y);
        h[1] = __floats2half2_rn(v0.z, v0.w);
        h[2] = __floats2half2_rn(v1.x, v1.y);
        h[3] = __floats2half2_rn(v1.z, v1.w);
        *reinterpret_cast<uint4*>(dst + i) = *reinterpret_cast<uint4*>(h);
    }
}

// ============================================================================
// 3-stage cp.async fp16 GEMM core, BK=64, ldmatrix loads, warp tile 64x64,
// 128 threads (2x2 warps).  C[M,N] = A[M,K] * B[N,K]^T.  (unchanged R15)
// ============================================================================
#define GH_BM 128
#define GH_BN 128
#define GH_BK 64
#define GH_S  3
#define GH_THR 128
#define GH_LDT 36                            // 32 data uints + 4 pad (64 halves)
#define GH_TILE (128 * GH_LDT)
#define GH_STG  (2 * GH_TILE)
#define GH_SMEM_BYTES (GH_S * GH_STG * 4)    // 110592 B
#define GH_MT 4
#define GH_NT 8

__device__ __forceinline__ void gemm_core_h(
    const __half* __restrict__ A,
    const __half* __restrict__ B,
    int Kdim, int m0, int n0,
    float (&acc)[GH_MT][GH_NT][4])
{
    extern __shared__ uint32_t smh[];
    const uint32_t sm_b = smem_u32(smh);

    const int tid  = threadIdx.x;
    const int lane = tid & 31;
    const int warp = tid >> 5;               // 0..3
    const int wm = (warp >> 1) * 64;
    const int wn = (warp & 1) * 64;
    const int mat  = lane >> 3;
    const int rin  = lane & 7;
    const int a_lrow = (mat & 1) * 8 + rin;
    const int a_lcol = (mat >> 1) * 4;
    const int b_sel  = (mat >> 1);
    const int b_lcol = (mat & 1) * 4;

    auto stage = [&](int chunk) {
        const int s = chunk % GH_S;
        const uint32_t ab = sm_b + (uint32_t)(s * GH_STG) * 4;
        const uint32_t bb = ab + GH_TILE * 4;
        const int k0 = chunk * GH_BK;
        #pragma unroll
        for (int i = 0; i < 8; ++i) {
            int idx = tid + i * GH_THR;
            int row = idx >> 3, q = idx & 7;
            cp16(ab + (uint32_t)(row * GH_LDT + q * 4) * 4,
                 A + (size_t)(m0 + row) * Kdim + k0 + q * 8);
            cp16(bb + (uint32_t)(row * GH_LDT + q * 4) * 4,
                 B + (size_t)(n0 + row) * Kdim + k0 + q * 8);
        }
    };

    auto compute = [&](int i) {
        const uint32_t ab = sm_b + (uint32_t)((i % GH_S) * GH_STG) * 4;
        const uint32_t bb = ab + GH_TILE * 4;
        #pragma unroll
        for (int ks = 0; ks < 4; ++ks) {
            uint32_t af[GH_MT][4];
            uint32_t bf[GH_NT][2];
            #pragma unroll
            for (int mt = 0; mt < GH_MT; ++mt) {
                uint32_t ad = ab + (uint32_t)((wm + mt * 16 + a_lrow) * GH_LDT
                                              + ks * 8 + a_lcol) * 4;
                ldsm4(af[mt][0], af[mt][1], af[mt][2], af[mt][3], ad);
            }
            #pragma unroll
            for (int p = 0; p < 4; ++p) {
                uint32_t bd = bb + (uint32_t)((wn + (2 * p + b_sel) * 8 + rin) * GH_LDT
                                              + ks * 8 + b_lcol) * 4;
                ldsm4(bf[2 * p][0], bf[2 * p][1], bf[2 * p + 1][0], bf[2 * p + 1][1], bd);
            }
            #pragma unroll
            for (int mt = 0; mt < GH_MT; ++mt)
                #pragma unroll
                for (int nt = 0; nt < GH_NT; ++nt)
                    mma16(acc[mt][nt], af[mt], bf[nt]);
        }
    };

    const int nchunk = Kdim / GH_BK;         // 16
    #pragma unroll
    for (int c = 0; c < GH_S - 1; ++c) {
        stage(c);
        asm volatile("cp.async.commit_group;\n");
    }

    int i = 0;
    for (; i < nchunk - (GH_S - 1); ++i) {
        asm volatile("cp.async.wait_group %0;\n" :: "n"(GH_S - 2));
        __syncthreads();
        compute(i);
        stage(i + GH_S - 1);
        asm volatile("cp.async.commit_group;\n");
    }
    asm volatile("cp.async.wait_group 0;\n");
    __syncthreads();
    for (; i < nchunk; ++i) compute(i);
}

// ---- kernel 1: fused QKV projection (grid.z selects q/k/v) ----
#define TR_LDC 136   // halves per c-row in transpose buffer (272 B pitch)

__global__ void __launch_bounds__(GH_THR, 2) qkv_kernel(
    const float* __restrict__ bq, const float* __restrict__ bk,
    const float* __restrict__ bv)
{
    extern __shared__ uint32_t smh[];
    const int z = blockIdx.z;
    const __half* W   = (z == 0) ? g_wqh : ((z == 1) ? g_wkh : g_wvh);
    const float* bptr = (z == 0) ? bq    : ((z == 1) ? bk    : bv);
    __half* out       = (z == 0) ? g_qh  : ((z == 1) ? g_kh  : g_vh);

    float acc[GH_MT][GH_NT][4] = {};
    const int m0 = blockIdx.x * GH_BM, n0 = blockIdx.y * GH_BN;
    gemm_core_h(g_xh, W, EMB, m0, n0, acc);

    const int lane = threadIdx.x & 31, warp = threadIdx.x >> 5;
    const int g = lane >> 2, tg = lane & 3;
    const int wm = (warp >> 1) * 64;
    const int wn = (warp & 1) * 64;

    if (z < 2) {
        #pragma unroll
        for (int mt = 0; mt < GH_MT; ++mt)
            #pragma unroll
            for (int nt = 0; nt < GH_NT; ++nt) {
                int r = m0 + wm + mt * 16 + g;
                int c = n0 + wn + nt * 8 + 2 * tg;       // even
                float v0 = acc[mt][nt][0] + bptr[c];
                float v1 = acc[mt][nt][1] + bptr[c + 1];
                float v2 = acc[mt][nt][2] + bptr[c];
                float v3 = acc[mt][nt][3] + bptr[c + 1];
                int h = c >> 6, d = c & 63;
                int b0 = r >> 10, s0 = r & 1023;
                int b1 = (r + 8) >> 10, s1 = (r + 8) & 1023;
                __half2* p0 = reinterpret_cast<__half2*>(
                    out + (((size_t)b0 * NH + h) * SEQ + s0) * HD + d);
                __half2* p1 = reinterpret_cast<__half2*>(
                    out + (((size_t)b1 * NH + h) * SEQ + s1) * HD + d);
                *p0 = __floats2half2_rn(v0, v1);
                *p1 = __floats2half2_rn(v2, v3);
            }
    } else {
        // V: transpose through smem, then coalesced [B,H,D,S] stores.
        __syncthreads();
        __half* tsm = reinterpret_cast<__half*>(smh);
        #pragma unroll
        for (int mt = 0; mt < GH_MT; ++mt)
            #pragma unroll
            for (int nt = 0; nt < GH_NT; ++nt) {
                int r  = wm + mt * 16 + g;
                int cl = wn + nt * 8 + 2 * tg;
                tsm[(cl    ) * TR_LDC + r    ] = __float2half_rn(acc[mt][nt][0] + bptr[n0 + cl]);
                tsm[(cl + 1) * TR_LDC + r    ] = __float2half_rn(acc[mt][nt][1] + bptr[n0 + cl + 1]);
                tsm[(cl    ) * TR_LDC + r + 8] = __float2half_rn(acc[mt][nt][2] + bptr[n0 + cl]);
                tsm[(cl + 1) * TR_LDC + r + 8] = __float2half_rn(acc[mt][nt][3] + bptr[n0 + cl + 1]);
            }
        __syncthreads();
        const int b0 = m0 >> 10, sbase = m0 & 1023;
        #pragma unroll
        for (int i = 0; i < 16; ++i) {
            int pid = threadIdx.x + i * GH_THR;
            int cc = pid >> 4;
            int rc = pid & 15;
            int cg = n0 + cc;
            int hh = cg >> 6, dd = cg & 63;
            uint4 val = *reinterpret_cast<uint4*>(tsm + cc * TR_LDC + rc * 8);
            *reinterpret_cast<uint4*>(
                out + (((size_t)b0 * NH + hh) * HD + dd) * SEQ + sbase + rc * 8) = val;
        }
    }
}

// ---- kernel 3: out = concat @ Wo^T + bo (fp32 output) ----
__global__ void __launch_bounds__(GH_THR, 2) oproj_kernel(
    const float* __restrict__ bo, float* __restrict__ out)
{
    float acc[GH_MT][GH_NT][4] = {};
    const int m0 = blockIdx.x * GH_BM, n0 = blockIdx.y * GH_BN;
    gemm_core_h(g_oh, g_woh, EMB, m0, n0, acc);

    const int lane = threadIdx.x & 31, warp = threadIdx.x >> 5;
    const int g = lane >> 2, tg = lane & 3;
    const int wm = (warp >> 1) * 64;
    const int wn = (warp & 1) * 64;
    #pragma unroll
    for (int mt = 0; mt < GH_MT; ++mt)
        #pragma unroll
        for (int nt = 0; nt < GH_NT; ++nt) {
            int r = m0 + wm + mt * 16 + g;
            int c = n0 + wn + nt * 8 + 2 * tg;
            out[(size_t)r * EMB + c]           = acc[mt][nt][0] + bo[c];
            out[(size_t)r * EMB + c + 1]       = acc[mt][nt][1] + bo[c + 1];
            out[(size_t)(r + 8) * EMB + c]     = acc[mt][nt][2] + bo[c];
            out[(size_t)(r + 8) * EMB + c + 1] = acc[mt][nt][3] + bo[c + 1];
        }
}

// ============================================================================
// kernel 2: fused flash attention — FA2 warp-row ownership, K/V ring-3,
// one barrier per tile, Q FRAGMENTS HOISTED to registers (loaded once).
// ============================================================================
#define FA_BM 128
#define FA_BN 64
#define FA_NT_TILES (SEQ / FA_BN)   // 16
#define FA_LDT 36
#define FA_QS (128 * FA_LDT)
#define FA_KS (64 * FA_LDT)
#define FA_VS (64 * FA_LDT)
#define FA_SMEM_BYTES ((FA_QS + 3 * FA_KS + 3 * FA_VS) * 4)   // 73728 B

__global__ void __launch_bounds__(256, 2) flash_kernel()
{
    extern __shared__ uint32_t fsh[];
    uint32_t* Qu = fsh;
    uint32_t* Ku = Qu + FA_QS;              // [3][64][36]
    uint32_t* Vu = Ku + 3 * FA_KS;          // [3][64][36]
    const uint32_t qu_b = smem_u32(Qu);
    const uint32_t ku_b = smem_u32(Ku);
    const uint32_t vu_b = smem_u32(Vu);

    const int z  = blockIdx.z;
    const int m0 = blockIdx.x * FA_BM;
    const __half* Qh = g_qh + (size_t)z * SEQ * HD;
    const __half* Kh = g_kh + (size_t)z * SEQ * HD;
    const __half* Vh = g_vh + (size_t)z * HD * SEQ;   // [D][S]

    const int tid  = threadIdx.x;
    const int lane = tid & 31, warp = tid >> 5;
    const int g = lane >> 2, tg = lane & 3;
    const int mat  = lane >> 3, rin = lane & 7;
    const int a_lrow = (mat & 1) * 8 + rin;
    const int a_lcol = (mat >> 1) * 4;
    const int b_sel  = (mat >> 1);
    const int b_lcol = (mat & 1) * 4;
    const int wrow = warp * 16;             // this warp's 16 rows

    auto stage_kv = [&](int t) {
        const int s = t % 3;
        const uint32_t kb = ku_b + (uint32_t)(s * FA_KS) * 4;
        const uint32_t vb = vu_b + (uint32_t)(s * FA_VS) * 4;
        const int n0 = t * FA_BN;
        #pragma unroll
        for (int i = 0; i < 2; ++i) {
            int idx = tid + i * 256;
            int rr = idx >> 3, q = idx & 7;
            cp16(kb + (uint32_t)(rr * FA_LDT + q * 4) * 4,
                 Kh + (size_t)(n0 + rr) * HD + q * 8);
            cp16(vb + (uint32_t)(rr * FA_LDT + q * 4) * 4,
                 Vh + (size_t)rr * SEQ + n0 + q * 8);
        }
    };

    // prologue: Q + tile 0 (group), tile 1 (group)
    #pragma unroll
    for (int i = 0; i < 4; ++i) {
        int idx = tid + i * 256;
        int r = idx >> 3, q = idx & 7;
        cp16(qu_b + (uint32_t)(r * FA_LDT + q * 4) * 4,
             Qh + (size_t)(m0 + r) * HD + q * 8);
    }
    stage_kv(0);
    asm volatile("cp.async.commit_group;\n");
    stage_kv(1);
    asm volatile("cp.async.commit_group;\n");

    float acc_o[8][4] = {};
    float m_st[2] = {-1e30f, -1e30f};
    float l_st[2] = {0.f, 0.f};
    uint32_t qf[4][4];                       // hoisted Q fragments (all ks)

    for (int t = 0; t < FA_NT_TILES; ++t) {
        if (t + 1 < FA_NT_TILES) {
            asm volatile("cp.async.wait_group 1;\n");
        } else {
            asm volatile("cp.async.wait_group 0;\n");
        }
        __syncthreads();

        if (t == 0) {
            // Q staged with tile 0; load all fragments once
            #pragma unroll
            for (int ks = 0; ks < 4; ++ks) {
                uint32_t ad = qu_b + (uint32_t)((wrow + a_lrow) * FA_LDT
                                                + ks * 8 + a_lcol) * 4;
                ldsm4(qf[ks][0], qf[ks][1], qf[ks][2], qf[ks][3], ad);
            }
        }

        const int s = t % 3;
        const uint32_t kub = ku_b + (uint32_t)(s * FA_KS) * 4;
        const uint32_t vub = vu_b + (uint32_t)(s * FA_VS) * 4;

        // ---- S = Q_w (16x64) K^T ----
        float acc_s[8][4] = {};
        #pragma unroll
        for (int ks = 0; ks < 4; ++ks) {
            uint32_t bf[8][2];
            #pragma unroll
            for (int p = 0; p < 4; ++p) {
                uint32_t bd = kub + (uint32_t)(((2 * p + b_sel) * 8 + rin) * FA_LDT
                                               + ks * 8 + b_lcol) * 4;
                ldsm4(bf[2 * p][0], bf[2 * p][1], bf[2 * p + 1][0], bf[2 * p + 1][1], bd);
            }
            #pragma unroll
            for (int nt = 0; nt < 8; ++nt)
                mma16(acc_s[nt], qf[ks], bf[nt]);
        }
        #pragma unroll
        for (int nt = 0; nt < 8; ++nt)
            #pragma unroll
            for (int e = 0; e < 4; ++e)
                acc_s[nt][e] *= 0.125f;

        // ---- warp-local online softmax; P packed into registers ----
        uint32_t plo[8], phi[8];
        #pragma unroll
        for (int h = 0; h < 2; ++h) {
            float m = -1e30f;
            #pragma unroll
            for (int nt = 0; nt < 8; ++nt)
                m = fmaxf(m, fmaxf(acc_s[nt][2 * h], acc_s[nt][2 * h + 1]));
            m = fmaxf(m, __shfl_xor_sync(0xffffffffu, m, 1));
            m = fmaxf(m, __shfl_xor_sync(0xffffffffu, m, 2));
            float mnew = fmaxf(m_st[h], m);
            float sc = __expf(m_st[h] - mnew);
            m_st[h] = mnew;
            l_st[h] *= sc;
            #pragma unroll
            for (int nt = 0; nt < 8; ++nt) {
                acc_o[nt][2 * h]     *= sc;
                acc_o[nt][2 * h + 1] *= sc;
            }
            float rs = 0.f;
            #pragma unroll
            for (int nt = 0; nt < 8; ++nt) {
                float p0 = __expf(acc_s[nt][2 * h]     - mnew);
                float p1 = __expf(acc_s[nt][2 * h + 1] - mnew);
                rs += p0 + p1;
                uint32_t pk = h2_bits(__floats2half2_rn(p0, p1));
                if (h == 0) plo[nt] = pk; else phi[nt] = pk;
            }
            rs += __shfl_xor_sync(0xffffffffu, rs, 1);
            rs += __shfl_xor_sync(0xffffffffu, rs, 2);
            l_st[h] += rs;
        }

        // ---- O += P V : P A-fragments straight from registers ----
        #pragma unroll
        for (int ks = 0; ks < 4; ++ks) {
            uint32_t af[4] = { plo[2 * ks], phi[2 * ks],
                               plo[2 * ks + 1], phi[2 * ks + 1] };
            uint32_t bf[8][2];
            #pragma unroll
            for (int p = 0; p < 4; ++p) {
                uint32_t bd = vub + (uint32_t)(((2 * p + b_sel) * 8 + rin) * FA_LDT
                                               + ks * 8 + b_lcol) * 4;
                ldsm4(bf[2 * p][0], bf[2 * p][1], bf[2 * p + 1][0], bf[2 * p + 1][1], bd);
            }
            #pragma unroll
            for (int nt = 0; nt < 8; ++nt)
                mma16(acc_o[nt], af, bf[nt]);
        }

        // stage tile t+2 into buf (t+2)%3 (freed by this iter's barrier)
        if (t + 2 < FA_NT_TILES) {
            stage_kv(t + 2);
            asm volatile("cp.async.commit_group;\n");
        }
    }

    // ---- epilogue: O /= l, half2 stores into concat layout [B,S,H*D] ----
    const int b = z >> 4, h = z & 15;
    const float inv0 = 1.0f / l_st[0];
    const float inv1 = 1.0f / l_st[1];
    const int s0 = m0 + wrow + g;
    #pragma unroll
    for (int nt = 0; nt < 8; ++nt) {
        int d0 = nt * 8 + 2 * tg;
        size_t base0 = ((size_t)(b * SEQ + s0)) * EMB + h * HD + d0;
        size_t base1 = ((size_t)(b * SEQ + s0 + 8)) * EMB + h * HD + d0;
        *reinterpret_cast<__half2*>(g_oh + base0) =
            __floats2half2_rn(acc_o[nt][0] * inv0, acc_o[nt][1] * inv0);
        *reinterpret_cast<__half2*>(g_oh + base1) =
            __floats2half2_rn(acc_o[nt][2] * inv1, acc_o[nt][3] * inv1);
    }
}

extern "C" void kernel_launch(void* const* d_in, const int* in_sizes, int n_in,
                              void* d_out, int out_size)
{
    const float* x  = (const float*)d_in[0];
    const float* Wq = (const float*)d_in[1];
    const float* bq = (const float*)d_in[2];
    const float* Wk = (const float*)d_in[3];
    const float* bk = (const float*)d_in[4];
    const float* Wv = (const float*)d_in[5];
    const float* bv = (const float*)d_in[6];
    const float* Wo = (const float*)d_in[7];
    const float* bo = (const float*)d_in[8];
    float* out = (float*)d_out;

    cudaFuncSetAttribute(qkv_kernel,
                         cudaFuncAttributeMaxDynamicSharedMemorySize, GH_SMEM_BYTES);
    cudaFuncSetAttribute(oproj_kernel,
                         cudaFuncAttributeMaxDynamicSharedMemorySize, GH_SMEM_BYTES);
    cudaFuncSetAttribute(flash_kernel,
                         cudaFuncAttributeMaxDynamicSharedMemorySize, FA_SMEM_BYTES);

    convert_kernel<<<dim3(512, 1, 5), 256>>>(x, Wq, Wk, Wv, Wo);
    qkv_kernel<<<dim3(MROWS / GH_BM, EMB / GH_BN, 3), GH_THR, GH_SMEM_BYTES>>>(bq, bk, bv);
    flash_kernel<<<dim3(SEQ / FA_BM, 1, BH), 256, FA_SMEM_BYTES>>>();
    oproj_kernel<<<dim3(MROWS / GH_BM, EMB / GH_BN, 1), GH_THR, GH_SMEM_BYTES>>>(bo, out);
}

// round 17
// speedup vs baseline: 1.2302x; 1.0410x over previous
#include <cuda_runtime.h>
#include <cuda_fp16.h>
#include <cstdint>
#include <cstddef>

#define BATCH 4
#define SEQ   1024
#define EMB   1024
#define NH    16
#define HD    64
#define BH    (BATCH * NH)      // 64
#define MROWS (BATCH * SEQ)     // 4096

// ---- scratch (device globals: allocation-free per harness rules) ----
__device__ __half g_xh[(size_t)MROWS * EMB];          // rounded x (8 MB)
__device__ __half g_wqh[(size_t)EMB * EMB];           // 2 MB each
__device__ __half g_wkh[(size_t)EMB * EMB];
__device__ __half g_wvh[(size_t)EMB * EMB];
__device__ __half g_woh[(size_t)EMB * EMB];
__device__ __half g_qh[(size_t)BH * SEQ * HD];        // [B,H,S,D]  (PRE-SCALED by 0.125)
__device__ __half g_kh[(size_t)BH * SEQ * HD];        // [B,H,S,D]
__device__ __half g_vh[(size_t)BH * SEQ * HD];        // [B,H,D,S]  (TRANSPOSED)
__device__ __half g_oh[(size_t)MROWS * EMB];          // [B,S,H*D] concat

// fp16 mma m16n8k16, fp32 accumulate
__device__ __forceinline__ void mma16(float* c, const uint32_t* a, const uint32_t* b) {
    asm volatile(
        "mma.sync.aligned.m16n8k16.row.col.f32.f16.f16.f32 "
        "{%0,%1,%2,%3}, {%4,%5,%6,%7}, {%8,%9}, {%0,%1,%2,%3};\n"
        : "+f"(c[0]), "+f"(c[1]), "+f"(c[2]), "+f"(c[3])
        : "r"(a[0]), "r"(a[1]), "r"(a[2]), "r"(a[3]),
          "r"(b[0]), "r"(b[1]));
}

__device__ __forceinline__ void cp16(uint32_t dst, const void* src) {
    asm volatile("cp.async.cg.shared.global [%0], [%1], 16;\n"
                 :: "r"(dst), "l"(src));
}

__device__ __forceinline__ void ldsm4(uint32_t& r0, uint32_t& r1,
                                      uint32_t& r2, uint32_t& r3, uint32_t addr) {
    asm volatile("ldmatrix.sync.aligned.m8n8.x4.shared.b16 {%0,%1,%2,%3}, [%4];"
                 : "=r"(r0), "=r"(r1), "=r"(r2), "=r"(r3) : "r"(addr));
}

__device__ __forceinline__ uint32_t smem_u32(const void* p) {
    uint32_t a;
    asm("{ .reg .u64 t; cvta.to.shared.u64 t, %1; cvt.u32.u64 %0, t; }"
        : "=r"(a) : "l"(p));
    return a;
}

__device__ __forceinline__ uint32_t h2_bits(__half2 h) {
    return *reinterpret_cast<uint32_t*>(&h);
}

// ---- kernel 0: convert inputs to fp16 (8 elems/thread, 16B stores) ----
__global__ void __launch_bounds__(256) convert_kernel(
    const float* __restrict__ x,
    const float* __restrict__ Wq, const float* __restrict__ Wk,
    const float* __restrict__ Wv, const float* __restrict__ Wo)
{
    const int z = blockIdx.z;
    const float* src;
    __half* dst;
    size_t n;
    if (z == 0)      { src = x;  dst = g_xh;  n = (size_t)MROWS * EMB; }
    else if (z == 1) { src = Wq; dst = g_wqh; n = (size_t)EMB * EMB; }
    else if (z == 2) { src = Wk; dst = g_wkh; n = (size_t)EMB * EMB; }
    else if (z == 3) { src = Wv; dst = g_wvh; n = (size_t)EMB * EMB; }
    else             { src = Wo; dst = g_woh; n = (size_t)EMB * EMB; }

    const size_t stride = (size_t)gridDim.x * blockDim.x * 8;
    for (size_t i = ((size_t)blockIdx.x * blockDim.x + threadIdx.x) * 8;
         i < n; i += stride) {
        float4 v0 = *reinterpret_cast<const float4*>(src + i);
        float4 v1 = *reinterpret_cast<const float4*>(src + i + 4);
        __half2 h[4];
        h[0] = __floats2half2_rn(v0.x, v0.y);
        h[1] = __floats2half2_rn(v0.z, v0.w);
        h[2] = __floats2half2_rn(v1.x, v1.y);
        h[3] = __floats2half2_rn(v1.z, v1.w);
        *reinterpret_cast<uint4*>(dst + i) = *reinterpret_cast<uint4*>(h);
    }
}

// ============================================================================
// 3-stage cp.async fp16 GEMM core, BK=64, ldmatrix loads, warp tile 64x64,
// 128 threads (2x2 warps).  C[M,N] = A[M,K] * B[N,K]^T.  (unchanged R15/16)
// ============================================================================
#define GH_BM 128
#define GH_BN 128
#define GH_BK 64
#define GH_S  3
#define GH_THR 128
#define GH_LDT 36                            // 32 data uints + 4 pad (64 halves)
#define GH_TILE (128 * GH_LDT)
#define GH_STG  (2 * GH_TILE)
#define GH_SMEM_BYTES (GH_S * GH_STG * 4)    // 110592 B
#define GH_MT 4
#define GH_NT 8

__device__ __forceinline__ void gemm_core_h(
    const __half* __restrict__ A,
    const __half* __restrict__ B,
    int Kdim, int m0, int n0,
    float (&acc)[GH_MT][GH_NT][4])
{
    extern __shared__ uint32_t smh[];
    const uint32_t sm_b = smem_u32(smh);

    const int tid  = threadIdx.x;
    const int lane = tid & 31;
    const int warp = tid >> 5;               // 0..3
    const int wm = (warp >> 1) * 64;
    const int wn = (warp & 1) * 64;
    const int mat  = lane >> 3;
    const int rin  = lane & 7;
    const int a_lrow = (mat & 1) * 8 + rin;
    const int a_lcol = (mat >> 1) * 4;
    const int b_sel  = (mat >> 1);
    const int b_lcol = (mat & 1) * 4;

    auto stage = [&](int chunk) {
        const int s = chunk % GH_S;
        const uint32_t ab = sm_b + (uint32_t)(s * GH_STG) * 4;
        const uint32_t bb = ab + GH_TILE * 4;
        const int k0 = chunk * GH_BK;
        #pragma unroll
        for (int i = 0; i < 8; ++i) {
            int idx = tid + i * GH_THR;
            int row = idx >> 3, q = idx & 7;
            cp16(ab + (uint32_t)(row * GH_LDT + q * 4) * 4,
                 A + (size_t)(m0 + row) * Kdim + k0 + q * 8);
            cp16(bb + (uint32_t)(row * GH_LDT + q * 4) * 4,
                 B + (size_t)(n0 + row) * Kdim + k0 + q * 8);
        }
    };

    auto compute = [&](int i) {
        const uint32_t ab = sm_b + (uint32_t)((i % GH_S) * GH_STG) * 4;
        const uint32_t bb = ab + GH_TILE * 4;
        #pragma unroll
        for (int ks = 0; ks < 4; ++ks) {
            uint32_t af[GH_MT][4];
            uint32_t bf[GH_NT][2];
            #pragma unroll
            for (int mt = 0; mt < GH_MT; ++mt) {
                uint32_t ad = ab + (uint32_t)((wm + mt * 16 + a_lrow) * GH_LDT
                                              + ks * 8 + a_lcol) * 4;
                ldsm4(af[mt][0], af[mt][1], af[mt][2], af[mt][3], ad);
            }
            #pragma unroll
            for (int p = 0; p < 4; ++p) {
                uint32_t bd = bb + (uint32_t)((wn + (2 * p + b_sel) * 8 + rin) * GH_LDT
                                              + ks * 8 + b_lcol) * 4;
                ldsm4(bf[2 * p][0], bf[2 * p][1], bf[2 * p + 1][0], bf[2 * p + 1][1], bd);
            }
            #pragma unroll
            for (int mt = 0; mt < GH_MT; ++mt)
                #pragma unroll
                for (int nt = 0; nt < GH_NT; ++nt)
                    mma16(acc[mt][nt], af[mt], bf[nt]);
        }
    };

    const int nchunk = Kdim / GH_BK;         // 16
    #pragma unroll
    for (int c = 0; c < GH_S - 1; ++c) {
        stage(c);
        asm volatile("cp.async.commit_group;\n");
    }

    int i = 0;
    for (; i < nchunk - (GH_S - 1); ++i) {
        asm volatile("cp.async.wait_group %0;\n" :: "n"(GH_S - 2));
        __syncthreads();
        compute(i);
        stage(i + GH_S - 1);
        asm volatile("cp.async.commit_group;\n");
    }
    asm volatile("cp.async.wait_group 0;\n");
    __syncthreads();
    for (; i < nchunk; ++i) compute(i);
}

// ---- kernel 1: fused QKV projection (grid.z selects q/k/v) ----
// q stored PRE-SCALED by 0.125 (exact power-of-2: commutes with fp16 round);
// k stored [B,H,S,D]; v stored TRANSPOSED [B,H,D,S] via smem-staged transpose.
#define TR_LDC 136   // halves per c-row in transpose buffer (272 B pitch)

__global__ void __launch_bounds__(GH_THR, 2) qkv_kernel(
    const float* __restrict__ bq, const float* __restrict__ bk,
    const float* __restrict__ bv)
{
    extern __shared__ uint32_t smh[];
    const int z = blockIdx.z;
    const __half* W   = (z == 0) ? g_wqh : ((z == 1) ? g_wkh : g_wvh);
    const float* bptr = (z == 0) ? bq    : ((z == 1) ? bk    : bv);
    __half* out       = (z == 0) ? g_qh  : ((z == 1) ? g_kh  : g_vh);
    const float osc   = (z == 0) ? 0.125f : 1.0f;   // fold 1/sqrt(D) into q

    float acc[GH_MT][GH_NT][4] = {};
    const int m0 = blockIdx.x * GH_BM, n0 = blockIdx.y * GH_BN;
    gemm_core_h(g_xh, W, EMB, m0, n0, acc);

    const int lane = threadIdx.x & 31, warp = threadIdx.x >> 5;
    const int g = lane >> 2, tg = lane & 3;
    const int wm = (warp >> 1) * 64;
    const int wn = (warp & 1) * 64;

    if (z < 2) {
        #pragma unroll
        for (int mt = 0; mt < GH_MT; ++mt)
            #pragma unroll
            for (int nt = 0; nt < GH_NT; ++nt) {
                int r = m0 + wm + mt * 16 + g;
                int c = n0 + wn + nt * 8 + 2 * tg;       // even
                float v0 = (acc[mt][nt][0] + bptr[c])     * osc;
                float v1 = (acc[mt][nt][1] + bptr[c + 1]) * osc;
                float v2 = (acc[mt][nt][2] + bptr[c])     * osc;
                float v3 = (acc[mt][nt][3] + bptr[c + 1]) * osc;
                int h = c >> 6, d = c & 63;
                int b0 = r >> 10, s0 = r & 1023;
                int b1 = (r + 8) >> 10, s1 = (r + 8) & 1023;
                __half2* p0 = reinterpret_cast<__half2*>(
                    out + (((size_t)b0 * NH + h) * SEQ + s0) * HD + d);
                __half2* p1 = reinterpret_cast<__half2*>(
                    out + (((size_t)b1 * NH + h) * SEQ + s1) * HD + d);
                *p0 = __floats2half2_rn(v0, v1);
                *p1 = __floats2half2_rn(v2, v3);
            }
    } else {
        // V: transpose through smem, then coalesced [B,H,D,S] stores.
        __syncthreads();
        __half* tsm = reinterpret_cast<__half*>(smh);
        #pragma unroll
        for (int mt = 0; mt < GH_MT; ++mt)
            #pragma unroll
            for (int nt = 0; nt < GH_NT; ++nt) {
                int r  = wm + mt * 16 + g;
                int cl = wn + nt * 8 + 2 * tg;
                tsm[(cl    ) * TR_LDC + r    ] = __float2half_rn(acc[mt][nt][0] + bptr[n0 + cl]);
                tsm[(cl + 1) * TR_LDC + r    ] = __float2half_rn(acc[mt][nt][1] + bptr[n0 + cl + 1]);
                tsm[(cl    ) * TR_LDC + r + 8] = __float2half_rn(acc[mt][nt][2] + bptr[n0 + cl]);
                tsm[(cl + 1) * TR_LDC + r + 8] = __float2half_rn(acc[mt][nt][3] + bptr[n0 + cl + 1]);
            }
        __syncthreads();
        const int b0 = m0 >> 10, sbase = m0 & 1023;
        #pragma unroll
        for (int i = 0; i < 16; ++i) {
            int pid = threadIdx.x + i * GH_THR;
            int cc = pid >> 4;
            int rc = pid & 15;
            int cg = n0 + cc;
            int hh = cg >> 6, dd = cg & 63;
            uint4 val = *reinterpret_cast<uint4*>(tsm + cc * TR_LDC + rc * 8);
            *reinterpret_cast<uint4*>(
                out + (((size_t)b0 * NH + hh) * HD + dd) * SEQ + sbase + rc * 8) = val;
        }
    }
}

// ---- kernel 3: out = concat @ Wo^T + bo (fp32 output, float2 stores) ----
__global__ void __launch_bounds__(GH_THR, 2) oproj_kernel(
    const float* __restrict__ bo, float* __restrict__ out)
{
    float acc[GH_MT][GH_NT][4] = {};
    const int m0 = blockIdx.x * GH_BM, n0 = blockIdx.y * GH_BN;
    gemm_core_h(g_oh, g_woh, EMB, m0, n0, acc);

    const int lane = threadIdx.x & 31, warp = threadIdx.x >> 5;
    const int g = lane >> 2, tg = lane & 3;
    const int wm = (warp >> 1) * 64;
    const int wn = (warp & 1) * 64;
    #pragma unroll
    for (int mt = 0; mt < GH_MT; ++mt)
        #pragma unroll
        for (int nt = 0; nt < GH_NT; ++nt) {
            int r = m0 + wm + mt * 16 + g;
            int c = n0 + wn + nt * 8 + 2 * tg;
            float2 w0 = make_float2(acc[mt][nt][0] + bo[c], acc[mt][nt][1] + bo[c + 1]);
            float2 w1 = make_float2(acc[mt][nt][2] + bo[c], acc[mt][nt][3] + bo[c + 1]);
            *reinterpret_cast<float2*>(out + (size_t)r * EMB + c)       = w0;
            *reinterpret_cast<float2*>(out + (size_t)(r + 8) * EMB + c) = w1;
        }
}

// ============================================================================
// kernel 2: fused flash attention — FA2 warp-row ownership, K/V ring-3,
// one barrier per tile, Q fragments hoisted, scale pre-folded into q.
// ============================================================================
#define FA_BM 128
#define FA_BN 64
#define FA_NT_TILES (SEQ / FA_BN)   // 16
#define FA_LDT 36
#define FA_QS (128 * FA_LDT)
#define FA_KS (64 * FA_LDT)
#define FA_VS (64 * FA_LDT)
#define FA_SMEM_BYTES ((FA_QS + 3 * FA_KS + 3 * FA_VS) * 4)   // 73728 B

__global__ void __launch_bounds__(256, 2) flash_kernel()
{
    extern __shared__ uint32_t fsh[];
    uint32_t* Qu = fsh;
    uint32_t* Ku = Qu + FA_QS;              // [3][64][36]
    uint32_t* Vu = Ku + 3 * FA_KS;          // [3][64][36]
    const uint32_t qu_b = smem_u32(Qu);
    const uint32_t ku_b = smem_u32(Ku);
    const uint32_t vu_b = smem_u32(Vu);

    const int z  = blockIdx.z;
    const int m0 = blockIdx.x * FA_BM;
    const __half* Qh = g_qh + (size_t)z * SEQ * HD;
    const __half* Kh = g_kh + (size_t)z * SEQ * HD;
    const __half* Vh = g_vh + (size_t)z * HD * SEQ;   // [D][S]

    const int tid  = threadIdx.x;
    const int lane = tid & 31, warp = tid >> 5;
    const int g = lane >> 2, tg = lane & 3;
    const int mat  = lane >> 3, rin = lane & 7;
    const int a_lrow = (mat & 1) * 8 + rin;
    const int a_lcol = (mat >> 1) * 4;
    const int b_sel  = (mat >> 1);
    const int b_lcol = (mat & 1) * 4;
    const int wrow = warp * 16;             // this warp's 16 rows

    auto stage_kv = [&](int t) {
        const int s = t % 3;
        const uint32_t kb = ku_b + (uint32_t)(s * FA_KS) * 4;
        const uint32_t vb = vu_b + (uint32_t)(s * FA_VS) * 4;
        const int n0 = t * FA_BN;
        #pragma unroll
        for (int i = 0; i < 2; ++i) {
            int idx = tid + i * 256;
            int rr = idx >> 3, q = idx & 7;
            cp16(kb + (uint32_t)(rr * FA_LDT + q * 4) * 4,
                 Kh + (size_t)(n0 + rr) * HD + q * 8);
            cp16(vb + (uint32_t)(rr * FA_LDT + q * 4) * 4,
                 Vh + (size_t)rr * SEQ + n0 + q * 8);
        }
    };

    // prologue: Q + tile 0 (group), tile 1 (group)
    #pragma unroll
    for (int i = 0; i < 4; ++i) {
        int idx = tid + i * 256;
        int r = idx >> 3, q = idx & 7;
        cp16(qu_b + (uint32_t)(r * FA_LDT + q * 4) * 4,
             Qh + (size_t)(m0 + r) * HD + q * 8);
    }
    stage_kv(0);
    asm volatile("cp.async.commit_group;\n");
    stage_kv(1);
    asm volatile("cp.async.commit_group;\n");

    float acc_o[8][4] = {};
    float m_st[2] = {-1e30f, -1e30f};
    float l_st[2] = {0.f, 0.f};
    uint32_t qf[4][4];                       // hoisted Q fragments

    for (int t = 0; t < FA_NT_TILES; ++t) {
        if (t + 1 < FA_NT_TILES) {
            asm volatile("cp.async.wait_group 1;\n");
        } else {
            asm volatile("cp.async.wait_group 0;\n");
        }
        __syncthreads();

        if (t == 0) {
            #pragma unroll
            for (int ks = 0; ks < 4; ++ks) {
                uint32_t ad = qu_b + (uint32_t)((wrow + a_lrow) * FA_LDT
                                                + ks * 8 + a_lcol) * 4;
                ldsm4(qf[ks][0], qf[ks][1], qf[ks][2], qf[ks][3], ad);
            }
        }

        const int s = t % 3;
        const uint32_t kub = ku_b + (uint32_t)(s * FA_KS) * 4;
        const uint32_t vub = vu_b + (uint32_t)(s * FA_VS) * 4;

        // ---- S = (0.125 Q)_w (16x64) K^T : scale already folded into q ----
        float acc_s[8][4] = {};
        #pragma unroll
        for (int ks = 0; ks < 4; ++ks) {
            uint32_t bf[8][2];
            #pragma unroll
            for (int p = 0; p < 4; ++p) {
                uint32_t bd = kub + (uint32_t)(((2 * p + b_sel) * 8 + rin) * FA_LDT
                                               + ks * 8 + b_lcol) * 4;
                ldsm4(bf[2 * p][0], bf[2 * p][1], bf[2 * p + 1][0], bf[2 * p + 1][1], bd);
            }
            #pragma unroll
            for (int nt = 0; nt < 8; ++nt)
                mma16(acc_s[nt], qf[ks], bf[nt]);
        }

        // ---- warp-local online softmax; P packed into registers ----
        uint32_t plo[8], phi[8];
        #pragma unroll
        for (int h = 0; h < 2; ++h) {
            float m = -1e30f;
            #pragma unroll
            for (int nt = 0; nt < 8; ++nt)
                m = fmaxf(m, fmaxf(acc_s[nt][2 * h], acc_s[nt][2 * h + 1]));
            m = fmaxf(m, __shfl_xor_sync(0xffffffffu, m, 1));
            m = fmaxf(m, __shfl_xor_sync(0xffffffffu, m, 2));
            float mnew = fmaxf(m_st[h], m);
            float sc = __expf(m_st[h] - mnew);
            m_st[h] = mnew;
            l_st[h] *= sc;
            #pragma unroll
            for (int nt = 0; nt < 8; ++nt) {
                acc_o[nt][2 * h]     *= sc;
                acc_o[nt][2 * h + 1] *= sc;
            }
            float rs = 0.f;
            #pragma unroll
            for (int nt = 0; nt < 8; ++nt) {
                float p0 = __expf(acc_s[nt][2 * h]     - mnew);
                float p1 = __expf(acc_s[nt][2 * h + 1] - mnew);
                rs += p0 + p1;
                uint32_t pk = h2_bits(__floats2half2_rn(p0, p1));
                if (h == 0) plo[nt] = pk; else phi[nt] = pk;
            }
            rs += __shfl_xor_sync(0xffffffffu, rs, 1);
            rs += __shfl_xor_sync(0xffffffffu, rs, 2);
            l_st[h] += rs;
        }

        // ---- O += P V : P A-fragments straight from registers ----
        #pragma unroll
        for (int ks = 0; ks < 4; ++ks) {
            uint32_t af[4] = { plo[2 * ks], phi[2 * ks],
                               plo[2 * ks + 1], phi[2 * ks + 1] };
            uint32_t bf[8][2];
            #pragma unroll
            for (int p = 0; p < 4; ++p) {
                uint32_t bd = vub + (uint32_t)(((2 * p + b_sel) * 8 + rin) * FA_LDT
                                               + ks * 8 + b_lcol) * 4;
                ldsm4(bf[2 * p][0], bf[2 * p][1], bf[2 * p + 1][0], bf[2 * p + 1][1], bd);
            }
            #pragma unroll
            for (int nt = 0; nt < 8; ++nt)
                mma16(acc_o[nt], af, bf[nt]);
        }

        if (t + 2 < FA_NT_TILES) {
            stage_kv(t + 2);
            asm volatile("cp.async.commit_group;\n");
        }
    }

    // ---- epilogue: O /= l, half2 stores into concat layout [B,S,H*D] ----
    const int b = z >> 4, h = z & 15;
    const float inv0 = 1.0f / l_st[0];
    const float inv1 = 1.0f / l_st[1];
    const int s0 = m0 + wrow + g;
    #pragma unroll
    for (int nt = 0; nt < 8; ++nt) {
        int d0 = nt * 8 + 2 * tg;
        size_t base0 = ((size_t)(b * SEQ + s0)) * EMB + h * HD + d0;
        size_t base1 = ((size_t)(b * SEQ + s0 + 8)) * EMB + h * HD + d0;
        *reinterpret_cast<__half2*>(g_oh + base0) =
            __floats2half2_rn(acc_o[nt][0] * inv0, acc_o[nt][1] * inv0);
        *reinterpret_cast<__half2*>(g_oh + base1) =
            __floats2half2_rn(acc_o[nt][2] * inv1, acc_o[nt][3] * inv1);
    }
}

extern "C" void kernel_launch(void* const* d_in, const int* in_sizes, int n_in,
                              void* d_out, int out_size)
{
    const float* x  = (const float*)d_in[0];
    const float* Wq = (const float*)d_in[1];
    const float* bq = (const float*)d_in[2];
    const float* Wk = (const float*)d_in[3];
    const float* bk = (const float*)d_in[4];
    const float* Wv = (const float*)d_in[5];
    const float* bv = (const float*)d_in[6];
    const float* Wo = (const float*)d_in[7];
    const float* bo = (const float*)d_in[8];
    float* out = (float*)d_out;

    cudaFuncSetAttribute(qkv_kernel,
                         cudaFuncAttributeMaxDynamicSharedMemorySize, GH_SMEM_BYTES);
    cudaFuncSetAttribute(oproj_kernel,
                         cudaFuncAttributeMaxDynamicSharedMemorySize, GH_SMEM_BYTES);
    cudaFuncSetAttribute(flash_kernel,
                         cudaFuncAttributeMaxDynamicSharedMemorySize, FA_SMEM_BYTES);

    convert_kernel<<<dim3(512, 1, 5), 256>>>(x, Wq, Wk, Wv, Wo);
    qkv_kernel<<<dim3(MROWS / GH_BM, EMB / GH_BN, 3), GH_THR, GH_SMEM_BYTES>>>(bq, bk, bv);
    flash_kernel<<<dim3(SEQ / FA_BM, 1, BH), 256, FA_SMEM_BYTES>>>();
    oproj_kernel<<<dim3(MROWS / GH_BM, EMB / GH_BN, 1), GH_THR, GH_SMEM_BYTES>>>(bo, out);
}